// round 10
// baseline (speedup 1.0000x reference)
#include <cuda_runtime.h>
#include <cmath>

// ---------------------------------------------------------------------------
// DecoderRNN (mma.sync path; tcgen05 rejected by harness ptxas target):
//  * gi table precompute (token -> 1536 gate inputs)
//  * per-step fused GEMM+GRU: m16n8k8 TF32 mma, 3-stage cp.async pipeline,
//    256 threads / 8 warps with 64x48 warp tiles, register-double-buffered
//    operand fragments (LDS overlapped with MMA), register GRU epilogue
//  * all 160 hidden states stored (tf32) -> ONE batched logits GEMM + fused
//    log_softmax at the end
// Output: [160*2048*128 log_probs fp32][2048*512 final hidden fp32]
// ---------------------------------------------------------------------------

#define HID   512
#define VOC   128
#define EMBD  64
#define BSZ   2048
#define TLEN  160
#define G3    1536

#define AS_LD  36      // A smem row stride (32 + 4)
#define BS_LD  200     // gru B smem row stride (192 + 8)
#define BS2_LD 136     // logits B smem row stride (128 + 8)
#define EP_LD  132     // logits epilogue stride

#define SBUF   (128 * AS_LD + 32 * BS_LD)    // 11008 floats per gru stage
#define NSTAGE 3
#define SBUF2  (128 * AS_LD + 32 * BS2_LD)   // logits stage

// Static scratch (module-load allocated)
__device__ float g_Wt  [HID * G3];                       // W_hh^T tf32 [k][n]
__device__ float g_WoT [HID * VOC];                      // W_out^T tf32 [k][v]
__device__ float g_GI  [VOC * G3];                       // gi table (incl b_ih)
__device__ float g_H   [2][BSZ * HID];                   // fp32 hidden ping-pong
__device__ float g_Hall[(size_t)(TLEN + 1) * BSZ * HID]; // tf32 hidden history

__device__ __forceinline__ float tf32r(float x) {
    unsigned u;
    asm("cvt.rna.tf32.f32 %0, %1;" : "=r"(u) : "f"(x));
    return __uint_as_float(u);
}

__device__ __forceinline__ void cpa16(float* dst, const float* src) {
    unsigned d = (unsigned)__cvta_generic_to_shared(dst);
    asm volatile("cp.async.cg.shared.global [%0], [%1], 16;" :: "r"(d), "l"(src));
}
#define CP_COMMIT() asm volatile("cp.async.commit_group;")
#define CP_WAIT(n)  asm volatile("cp.async.wait_group %0;" :: "n"(n))

__device__ __forceinline__ void mma8(float d[4], const unsigned a[4],
                                     unsigned b0, unsigned b1) {
    asm volatile("mma.sync.aligned.m16n8k8.row.col.f32.tf32.tf32.f32 "
                 "{%0,%1,%2,%3}, {%4,%5,%6,%7}, {%8,%9}, {%0,%1,%2,%3};"
                 : "+f"(d[0]), "+f"(d[1]), "+f"(d[2]), "+f"(d[3])
                 : "r"(a[0]), "r"(a[1]), "r"(a[2]), "r"(a[3]), "r"(b0), "r"(b1));
}

// ---------------------------------------------------------------------------
// Precompute
// ---------------------------------------------------------------------------
__global__ void prep_w(const float* __restrict__ Whh, const float* __restrict__ Wout) {
    const int n1 = HID * G3, ntot = n1 + HID * VOC;
    for (int idx = blockIdx.x * blockDim.x + threadIdx.x; idx < ntot;
         idx += gridDim.x * blockDim.x) {
        if (idx < n1) {
            int n = idx / HID, k = idx % HID;
            g_Wt[k * G3 + n] = tf32r(Whh[idx]);
        } else {
            int j = idx - n1, v = j / HID, k = j % HID;
            g_WoT[k * VOC + v] = tf32r(Wout[j]);
        }
    }
}

__global__ void prep_gi(const float* __restrict__ emb, const float* __restrict__ Wih,
                        const float* __restrict__ bih) {
    __shared__ float x[EMBD];
    const int v = blockIdx.x;
    if (threadIdx.x < EMBD) x[threadIdx.x] = fmaxf(emb[v * EMBD + threadIdx.x], 0.f);
    __syncthreads();
    for (int n = threadIdx.x; n < G3; n += blockDim.x) {
        float acc = bih[n];
        const float* w = Wih + n * EMBD;
#pragma unroll
        for (int e = 0; e < EMBD; e++) acc += x[e] * w[e];
        g_GI[v * G3 + n] = acc;
    }
}

__global__ void init_h(const float* __restrict__ eh) {
    for (int i = blockIdx.x * blockDim.x + threadIdx.x; i < BSZ * HID;
         i += gridDim.x * blockDim.x) {
        float h = eh[i];
        g_H[0][i] = h;
        g_Hall[i] = tf32r(h);   // slot 0
    }
}

// ---------------------------------------------------------------------------
// GRU step. Grid (8 j-tiles, 16 m-tiles), 256 threads = 8 warps (2M x 4N).
// CTA tile: 128 rows x 64 hidden cols x 3 gates (N=192, gate-interleaved).
// Warp tile: 64(M) x 48(N). 3-stage cp.async; register-double-buffered frags.
// ---------------------------------------------------------------------------
__global__ void __launch_bounds__(256, 1)
gru_step(int t, const int* __restrict__ tgt, const float* __restrict__ bhh) {
    extern __shared__ float sm[];

    const int tid  = threadIdx.x;
    const int lane = tid & 31, w = tid >> 5;
    const int l3 = lane & 3, q2 = lane >> 2;
    const int wm = (w >> 2) * 64;      // warp M offset (0 or 64)
    const int wn = (w & 3);            // warp N group (16 jj cols)
    const int m0 = blockIdx.y * 128;
    const int j0 = blockIdx.x * 64;

    const int cur = t & 1, nxt = cur ^ 1;
    const float* __restrict__ A = g_Hall + (size_t)t * BSZ * HID;

    float d[4][6][4];
#pragma unroll
    for (int a = 0; a < 4; a++)
#pragma unroll
        for (int b = 0; b < 6; b++)
#pragma unroll
            for (int c = 0; c < 4; c++) d[a][b][c] = 0.f;

    // ---- tile loader (cp.async, 256 threads) ----
    auto load_tile = [&](int buf, int kt) {
        float* As = sm + buf * SBUF;
        float* Bs = As + 128 * AS_LD;
        const int k0 = kt * 32;
#pragma unroll
        for (int i = 0; i < 4; i++) {              // A: 128x32
            int f = i * 256 + tid, row = f >> 3, q = f & 7;
            cpa16(As + row * AS_LD + q * 4,
                  A + (size_t)(m0 + row) * HID + k0 + q * 4);
        }
#pragma unroll
        for (int i = 0; i < 6; i++) {              // B: 32x192 gate-interleaved
            int f = i * 256 + tid;
            int k = f / 48, rest = f % 48;
            int g = rest >> 4, q = rest & 15;
            int c = (q >> 2) * 48 + g * 16 + (q & 3) * 4;
            cpa16(Bs + k * BS_LD + c,
                  g_Wt + (size_t)(k0 + k) * G3 + g * HID + j0 + q * 4);
        }
    };

    // ---- fragment loaders ----
    unsigned af[2][4][4], bf[2][6][2];
    auto ld_frags = [&](int fb, const float* As, const float* Bs, int kk) {
#pragma unroll
        for (int mf = 0; mf < 4; mf++) {
            int row = wm + mf * 16 + q2;
            af[fb][mf][0] = __float_as_uint(As[row * AS_LD + kk + l3]);
            af[fb][mf][1] = __float_as_uint(As[(row + 8) * AS_LD + kk + l3]);
            af[fb][mf][2] = __float_as_uint(As[row * AS_LD + kk + 4 + l3]);
            af[fb][mf][3] = __float_as_uint(As[(row + 8) * AS_LD + kk + 4 + l3]);
        }
#pragma unroll
        for (int nf = 0; nf < 6; nf++) {
            int col = wn * 48 + nf * 8 + q2;
            bf[fb][nf][0] = __float_as_uint(Bs[(kk + l3) * BS_LD + col]);
            bf[fb][nf][1] = __float_as_uint(Bs[(kk + 4 + l3) * BS_LD + col]);
        }
    };

    // ---- prologue: start 2 tiles, wait for tile 0, prefetch its first frags
    load_tile(0, 0); CP_COMMIT();
    load_tile(1, 1); CP_COMMIT();
    CP_WAIT(1);
    __syncthreads();
    ld_frags(0, sm, sm + 128 * AS_LD, 0);

    for (int kt = 0; kt < 16; kt++) {
        const int buf = kt % NSTAGE;
        const float* As = sm + buf * SBUF;
        const float* Bs = As + 128 * AS_LD;
#pragma unroll
        for (int ks = 0; ks < 4; ks++) {
            const int cb = ks & 1, nb = cb ^ 1;
            if (ks < 3) ld_frags(nb, As, Bs, (ks + 1) * 8);   // overlap LDS w/ MMA
#pragma unroll
            for (int nf = 0; nf < 6; nf++) {
#pragma unroll
                for (int mf = 0; mf < 4; mf++)
                    mma8(d[mf][nf], af[cb][mf], bf[cb][nf][0], bf[cb][nf][1]);
            }
        }
        if (kt < 15) {
            if (kt + 2 < 16) { load_tile((kt + 2) % NSTAGE, kt + 2); CP_COMMIT(); }
            if (kt + 2 < 16) CP_WAIT(1); else CP_WAIT(0);   // tile kt+1 resident
            __syncthreads();
            const float* nAs = sm + ((kt + 1) % NSTAGE) * SBUF;
            ld_frags(0, nAs, nAs + 128 * AS_LD, 0);
        }
    }

    // ---- register GRU epilogue ----
    const float* __restrict__ Hc = g_H[cur];
    float* __restrict__ Hn  = g_H[nxt];
    float* __restrict__ Ha  = g_Hall + (size_t)(t + 1) * BSZ * HID;
#pragma unroll
    for (int mf = 0; mf < 4; mf++) {
#pragma unroll
        for (int rh = 0; rh < 2; rh++) {
            const int row = m0 + wm + mf * 16 + q2 + rh * 8;
            const int tok = (t == 0) ? 0 : __ldg(tgt + row * TLEN + t - 1);
            const float* __restrict__ gi = g_GI + tok * G3;
#pragma unroll
            for (int jf = 0; jf < 2; jf++) {
                const int j2 = j0 + wn * 16 + jf * 8 + l3 * 2;
                float h[2], ht[2];
#pragma unroll
                for (int p = 0; p < 2; p++) {
                    const int r = rh * 2 + p;
                    const int j = j2 + p;
                    float gr  = d[mf][jf][r]     + bhh[j]         + gi[j];
                    float gz  = d[mf][2 + jf][r] + bhh[HID + j]   + gi[HID + j];
                    float ghn = d[mf][4 + jf][r] + bhh[2*HID + j];
                    float rr = 1.f / (1.f + expf(-gr));
                    float zz = 1.f / (1.f + expf(-gz));
                    float nn = tanhf(gi[2*HID + j] + rr * ghn);
                    float ho = Hc[(size_t)row * HID + j];
                    h[p]  = fmaf(zz, ho - nn, nn);   // (1-z)n + z*ho
                    ht[p] = tf32r(h[p]);
                }
                *reinterpret_cast<float2*>(Hn + (size_t)row * HID + j2) =
                    make_float2(h[0], h[1]);
                *reinterpret_cast<float2*>(Ha + (size_t)row * HID + j2) =
                    make_float2(ht[0], ht[1]);
            }
        }
    }
}

// ---------------------------------------------------------------------------
// Batched logits: (160*2048) x 128 x 512 GEMM + fused row log_softmax.
// Grid 2560 (M-tiles of 128). 256 threads = 8 warps (4M x 2N), warp 32x64.
// ---------------------------------------------------------------------------
__global__ void __launch_bounds__(256, 1)
logits_all(const float* __restrict__ bout, float* __restrict__ out) {
    extern __shared__ float sm[];
    float* ep = sm;

    const int tid = threadIdx.x, lane = tid & 31, w = tid >> 5;
    const int l3 = lane & 3, q2 = lane >> 2;
    const int wm = (w >> 1) * 32, wn = (w & 1) * 64;
    const int m0 = blockIdx.x * 128;

    const float* __restrict__ A = g_Hall + (size_t)BSZ * HID;   // slots 1..160

    float d[2][8][4];
#pragma unroll
    for (int a = 0; a < 2; a++)
#pragma unroll
        for (int b = 0; b < 8; b++)
#pragma unroll
            for (int c = 0; c < 4; c++) d[a][b][c] = 0.f;

    auto load_tile = [&](int buf, int k0) {
        float* As = sm + buf * SBUF2;
        float* Bs = As + 128 * AS_LD;
#pragma unroll
        for (int i = 0; i < 4; i++) {
            int f = i * 256 + tid, row = f >> 3, q = f & 7;
            cpa16(As + row * AS_LD + q * 4, A + (size_t)(m0 + row) * HID + k0 + q * 4);
        }
#pragma unroll
        for (int i = 0; i < 4; i++) {
            int f = i * 256 + tid, k = f >> 5, q = f & 31;
            cpa16(Bs + k * BS2_LD + q * 4, g_WoT + (k0 + k) * VOC + q * 4);
        }
    };

    load_tile(0, 0);
    CP_COMMIT();
    CP_WAIT(0);
    __syncthreads();

    for (int kt = 0; kt < 16; kt++) {
        if (kt < 15) { load_tile((kt + 1) & 1, (kt + 1) * 32); CP_COMMIT(); }
        const float* As = sm + (kt & 1) * SBUF2;
        const float* Bs = As + 128 * AS_LD;
#pragma unroll
        for (int ks = 0; ks < 4; ks++) {
            const int kk = ks * 8;
            unsigned a[2][4];
#pragma unroll
            for (int mf = 0; mf < 2; mf++) {
                int r = wm + mf * 16 + q2;
                a[mf][0] = __float_as_uint(As[r * AS_LD + kk + l3]);
                a[mf][1] = __float_as_uint(As[(r + 8) * AS_LD + kk + l3]);
                a[mf][2] = __float_as_uint(As[r * AS_LD + kk + 4 + l3]);
                a[mf][3] = __float_as_uint(As[(r + 8) * AS_LD + kk + 4 + l3]);
            }
#pragma unroll
            for (int nf = 0; nf < 8; nf++) {
                int col = wn + nf * 8 + q2;
                unsigned b0 = __float_as_uint(Bs[(kk + l3) * BS2_LD + col]);
                unsigned b1 = __float_as_uint(Bs[(kk + 4 + l3) * BS2_LD + col]);
                mma8(d[0][nf], a[0], b0, b1);
                mma8(d[1][nf], a[1], b0, b1);
            }
        }
        if (kt < 15) { CP_WAIT(0); __syncthreads(); }
    }

    __syncthreads();

#pragma unroll
    for (int mf = 0; mf < 2; mf++)
#pragma unroll
        for (int nf = 0; nf < 8; nf++)
#pragma unroll
            for (int rh = 0; rh < 2; rh++) {
                int r = wm + mf * 16 + q2 + rh * 8;
                int col = wn + nf * 8 + l3 * 2;
                *reinterpret_cast<float2*>(ep + r * EP_LD + col) =
                    make_float2(d[mf][nf][rh * 2], d[mf][nf][rh * 2 + 1]);
            }
    __syncthreads();

    for (int i = 0; i < 16; i++) {
        int row = w * 16 + i;
        float x[4];
        float mx = -1e30f;
#pragma unroll
        for (int q = 0; q < 4; q++) {
            int v = lane + q * 32;
            x[q] = ep[row * EP_LD + v] + bout[v];
            mx = fmaxf(mx, x[q]);
        }
#pragma unroll
        for (int off = 16; off > 0; off >>= 1)
            mx = fmaxf(mx, __shfl_xor_sync(0xffffffffu, mx, off));
        float s = 0.f;
#pragma unroll
        for (int q = 0; q < 4; q++) s += expf(x[q] - mx);
#pragma unroll
        for (int off = 16; off > 0; off >>= 1)
            s += __shfl_xor_sync(0xffffffffu, s, off);
        float L = mx + logf(s);
        float* orow = out + (size_t)(m0 + row) * VOC;
#pragma unroll
        for (int q = 0; q < 4; q++) orow[lane + q * 32] = x[q] - L;
    }
}

__global__ void finalize_h(float* __restrict__ out) {
    float* dst = out + (size_t)TLEN * BSZ * VOC;
    for (int i = blockIdx.x * blockDim.x + threadIdx.x; i < BSZ * HID;
         i += gridDim.x * blockDim.x)
        dst[i] = g_H[0][i];   // after t=159: nxt = 0
}

// ---------------------------------------------------------------------------
extern "C" void kernel_launch(void* const* d_in, const int* in_sizes, int n_in,
                              void* d_out, int out_size) {
    (void)in_sizes; (void)n_in; (void)out_size;
    const float* enc_h = (const float*)d_in[1];
    const int*   tgt   = (const int*)d_in[2];
    const float* emb   = (const float*)d_in[3];
    const float* Wih   = (const float*)d_in[4];
    const float* Whh   = (const float*)d_in[5];
    const float* bih   = (const float*)d_in[6];
    const float* bhh   = (const float*)d_in[7];
    const float* Wout  = (const float*)d_in[8];
    const float* bout  = (const float*)d_in[9];
    float* out = (float*)d_out;

    const int gru_smem = NSTAGE * SBUF * 4;   // 132096 B
    const int log_smem = 2 * SBUF2 * 4;       // 71680 B
    cudaFuncSetAttribute(gru_step,   cudaFuncAttributeMaxDynamicSharedMemorySize, gru_smem);
    cudaFuncSetAttribute(logits_all, cudaFuncAttributeMaxDynamicSharedMemorySize, log_smem);

    prep_w <<<512, 256>>>(Whh, Wout);
    prep_gi<<<VOC, 256>>>(emb, Wih, bih);
    init_h <<<1024, 256>>>(enc_h);

    for (int t = 0; t < TLEN; t++)
        gru_step<<<dim3(8, 16), 256, gru_smem>>>(t, tgt, bhh);

    logits_all<<<(TLEN * BSZ) / 128, 256, log_smem>>>(bout, out);
    finalize_h<<<1024, 256>>>(out);
}

// round 11
// speedup vs baseline: 1.0645x; 1.0645x over previous
#include <cuda_runtime.h>
#include <cmath>

// ---------------------------------------------------------------------------
// DecoderRNN (mma.sync; tcgen05 unavailable on this ptxas target):
//  * gi table precompute (token -> 1536 gate inputs)
//  * per-step fused GEMM+GRU: m16n8k8 TF32 mma, 3-stage cp.async pipeline,
//    256 CTAs x 256 threads (2 CTAs/SM for barrier-desynchronized overlap),
//    CTA tile 128M x 96N (32 jj x 3 gates), warp tile 32x48, register epilogue
//  * all 160 hidden states stored (tf32) -> ONE batched logits GEMM + fused
//    log_softmax at the end
// Output: [160*2048*128 log_probs fp32][2048*512 final hidden fp32]
// ---------------------------------------------------------------------------

#define HID   512
#define VOC   128
#define EMBD  64
#define BSZ   2048
#define TLEN  160
#define G3    1536

#define AS_LD  36      // A smem row stride (32 + 4)
#define BS_LD  104     // gru B smem row stride (96 + 8)
#define BS2_LD 136     // logits B smem row stride (128 + 8)
#define EP_LD  132     // logits epilogue stride

#define SBUF   (128 * AS_LD + 32 * BS_LD)    // 7936 floats per gru stage
#define NSTAGE 3
#define SBUF2  (128 * AS_LD + 32 * BS2_LD)   // logits stage

// Static scratch (module-load allocated)
__device__ float g_Wt  [HID * G3];                       // W_hh^T tf32 [k][n]
__device__ float g_WoT [HID * VOC];                      // W_out^T tf32 [k][v]
__device__ float g_GI  [VOC * G3];                       // gi table (incl b_ih)
__device__ float g_H   [2][BSZ * HID];                   // fp32 hidden ping-pong
__device__ float g_Hall[(size_t)(TLEN + 1) * BSZ * HID]; // tf32 hidden history

__device__ __forceinline__ float tf32r(float x) {
    unsigned u;
    asm("cvt.rna.tf32.f32 %0, %1;" : "=r"(u) : "f"(x));
    return __uint_as_float(u);
}

__device__ __forceinline__ void cpa16(float* dst, const float* src) {
    unsigned d = (unsigned)__cvta_generic_to_shared(dst);
    asm volatile("cp.async.cg.shared.global [%0], [%1], 16;" :: "r"(d), "l"(src));
}
#define CP_COMMIT() asm volatile("cp.async.commit_group;")
#define CP_WAIT(n)  asm volatile("cp.async.wait_group %0;" :: "n"(n))

__device__ __forceinline__ void mma8(float d[4], const unsigned a[4],
                                     unsigned b0, unsigned b1) {
    asm volatile("mma.sync.aligned.m16n8k8.row.col.f32.tf32.tf32.f32 "
                 "{%0,%1,%2,%3}, {%4,%5,%6,%7}, {%8,%9}, {%0,%1,%2,%3};"
                 : "+f"(d[0]), "+f"(d[1]), "+f"(d[2]), "+f"(d[3])
                 : "r"(a[0]), "r"(a[1]), "r"(a[2]), "r"(a[3]), "r"(b0), "r"(b1));
}

// ---------------------------------------------------------------------------
// Precompute
// ---------------------------------------------------------------------------
__global__ void prep_w(const float* __restrict__ Whh, const float* __restrict__ Wout) {
    const int n1 = HID * G3, ntot = n1 + HID * VOC;
    for (int idx = blockIdx.x * blockDim.x + threadIdx.x; idx < ntot;
         idx += gridDim.x * blockDim.x) {
        if (idx < n1) {
            int n = idx / HID, k = idx % HID;
            g_Wt[k * G3 + n] = tf32r(Whh[idx]);
        } else {
            int j = idx - n1, v = j / HID, k = j % HID;
            g_WoT[k * VOC + v] = tf32r(Wout[j]);
        }
    }
}

__global__ void prep_gi(const float* __restrict__ emb, const float* __restrict__ Wih,
                        const float* __restrict__ bih) {
    __shared__ float x[EMBD];
    const int v = blockIdx.x;
    if (threadIdx.x < EMBD) x[threadIdx.x] = fmaxf(emb[v * EMBD + threadIdx.x], 0.f);
    __syncthreads();
    for (int n = threadIdx.x; n < G3; n += blockDim.x) {
        float acc = bih[n];
        const float* w = Wih + n * EMBD;
#pragma unroll
        for (int e = 0; e < EMBD; e++) acc += x[e] * w[e];
        g_GI[v * G3 + n] = acc;
    }
}

__global__ void init_h(const float* __restrict__ eh) {
    for (int i = blockIdx.x * blockDim.x + threadIdx.x; i < BSZ * HID;
         i += gridDim.x * blockDim.x) {
        float h = eh[i];
        g_H[0][i] = h;
        g_Hall[i] = tf32r(h);   // slot 0
    }
}

// ---------------------------------------------------------------------------
// GRU step. Grid (16 j-tiles, 16 m-tiles) = 256 CTAs, 256 threads = 8 warps.
// CTA tile: 128 rows x 32 jj x 3 gates (N=96, gate-interleaved per 16-jj block).
// Warps: 4(M) x 2(N); warp tile 32(M) x 48(N) — same fragment mapping as R8.
// 3-stage cp.async pipeline; 2 CTAs/SM for cross-CTA latency hiding.
// ---------------------------------------------------------------------------
__global__ void __launch_bounds__(256, 2)
gru_step(int t, const int* __restrict__ tgt, const float* __restrict__ bhh) {
    extern __shared__ float sm[];

    const int tid  = threadIdx.x;
    const int lane = tid & 31, w = tid >> 5;
    const int l3 = lane & 3, q2 = lane >> 2;
    const int wm = (w >> 1) * 32;      // warp M offset (0,32,64,96)
    const int wn = (w & 1);            // warp N group (16 jj cols)
    const int m0 = blockIdx.y * 128;
    const int j0 = blockIdx.x * 32;

    const int cur = t & 1, nxt = cur ^ 1;
    const float* __restrict__ A = g_Hall + (size_t)t * BSZ * HID;

    float d[2][6][4];
#pragma unroll
    for (int a = 0; a < 2; a++)
#pragma unroll
        for (int b = 0; b < 6; b++)
#pragma unroll
            for (int c = 0; c < 4; c++) d[a][b][c] = 0.f;

    // ---- tile loader (cp.async) ----
    auto load_tile = [&](int buf, int kt) {
        float* As = sm + buf * SBUF;
        float* Bs = As + 128 * AS_LD;
        const int k0 = kt * 32;
#pragma unroll
        for (int i = 0; i < 4; i++) {              // A: 128x32
            int f = i * 256 + tid, row = f >> 3, q = f & 7;
            cpa16(As + row * AS_LD + q * 4,
                  A + (size_t)(m0 + row) * HID + k0 + q * 4);
        }
#pragma unroll
        for (int i = 0; i < 3; i++) {              // B: 32x96 gate-interleaved
            int f = i * 256 + tid;
            int k = f / 24, q = f % 24;            // q: 24 float4 per k-row
            int blk = q / 12, rem = q % 12;
            int g = rem >> 2, w4 = rem & 3;
            cpa16(Bs + k * BS_LD + blk * 48 + g * 16 + w4 * 4,
                  g_Wt + (size_t)(k0 + k) * G3 + g * HID + j0 + blk * 16 + w4 * 4);
        }
    };

    // ---- prologue: stages 0,1 in flight; stage 0 resident ----
    load_tile(0, 0); CP_COMMIT();
    load_tile(1, 1); CP_COMMIT();
    CP_WAIT(1);
    __syncthreads();

    for (int kt = 0; kt < 16; kt++) {
        const float* As = sm + (kt % NSTAGE) * SBUF;
        const float* Bs = As + 128 * AS_LD;
#pragma unroll
        for (int ks = 0; ks < 4; ks++) {
            const int kk = ks * 8;
            unsigned a[2][4];
#pragma unroll
            for (int mf = 0; mf < 2; mf++) {
                int row = wm + mf * 16 + q2;
                a[mf][0] = __float_as_uint(As[row * AS_LD + kk + l3]);
                a[mf][1] = __float_as_uint(As[(row + 8) * AS_LD + kk + l3]);
                a[mf][2] = __float_as_uint(As[row * AS_LD + kk + 4 + l3]);
                a[mf][3] = __float_as_uint(As[(row + 8) * AS_LD + kk + 4 + l3]);
            }
#pragma unroll
            for (int nf = 0; nf < 6; nf++) {
                int col = wn * 48 + nf * 8 + q2;
                unsigned b0 = __float_as_uint(Bs[(kk + l3) * BS_LD + col]);
                unsigned b1 = __float_as_uint(Bs[(kk + 4 + l3) * BS_LD + col]);
                mma8(d[0][nf], a[0], b0, b1);
                mma8(d[1][nf], a[1], b0, b1);
            }
        }
        if (kt < 15) {
            if (kt + 2 < 16) {
                load_tile((kt + 2) % NSTAGE, kt + 2); CP_COMMIT();
                CP_WAIT(1);                         // tile kt+1 resident
            } else {
                CP_WAIT(0);
            }
            __syncthreads();
        }
    }

    // ---- register GRU epilogue ----
    const float* __restrict__ Hc = g_H[cur];
    float* __restrict__ Hn  = g_H[nxt];
    float* __restrict__ Ha  = g_Hall + (size_t)(t + 1) * BSZ * HID;
#pragma unroll
    for (int mf = 0; mf < 2; mf++) {
#pragma unroll
        for (int rh = 0; rh < 2; rh++) {
            const int row = m0 + wm + mf * 16 + q2 + rh * 8;
            const int tok = (t == 0) ? 0 : __ldg(tgt + row * TLEN + t - 1);
            const float* __restrict__ gi = g_GI + tok * G3;
#pragma unroll
            for (int jf = 0; jf < 2; jf++) {
                const int j2 = j0 + wn * 16 + jf * 8 + l3 * 2;
                float h[2], ht[2];
#pragma unroll
                for (int p = 0; p < 2; p++) {
                    const int r = rh * 2 + p;
                    const int j = j2 + p;
                    float gr  = d[mf][jf][r]     + bhh[j]         + gi[j];
                    float gz  = d[mf][2 + jf][r] + bhh[HID + j]   + gi[HID + j];
                    float ghn = d[mf][4 + jf][r] + bhh[2*HID + j];
                    float rr = 1.f / (1.f + expf(-gr));
                    float zz = 1.f / (1.f + expf(-gz));
                    float nn = tanhf(gi[2*HID + j] + rr * ghn);
                    float ho = Hc[(size_t)row * HID + j];
                    h[p]  = fmaf(zz, ho - nn, nn);   // (1-z)n + z*ho
                    ht[p] = tf32r(h[p]);
                }
                *reinterpret_cast<float2*>(Hn + (size_t)row * HID + j2) =
                    make_float2(h[0], h[1]);
                *reinterpret_cast<float2*>(Ha + (size_t)row * HID + j2) =
                    make_float2(ht[0], ht[1]);
            }
        }
    }
}

// ---------------------------------------------------------------------------
// Batched logits: (160*2048) x 128 x 512 GEMM + fused row log_softmax.
// Grid 2560 (M-tiles of 128). 256 threads = 8 warps (4M x 2N), warp 32x64.
// ---------------------------------------------------------------------------
__global__ void __launch_bounds__(256, 1)
logits_all(const float* __restrict__ bout, float* __restrict__ out) {
    extern __shared__ float sm[];
    float* ep = sm;

    const int tid = threadIdx.x, lane = tid & 31, w = tid >> 5;
    const int l3 = lane & 3, q2 = lane >> 2;
    const int wm = (w >> 1) * 32, wn = (w & 1) * 64;
    const int m0 = blockIdx.x * 128;

    const float* __restrict__ A = g_Hall + (size_t)BSZ * HID;   // slots 1..160

    float d[2][8][4];
#pragma unroll
    for (int a = 0; a < 2; a++)
#pragma unroll
        for (int b = 0; b < 8; b++)
#pragma unroll
            for (int c = 0; c < 4; c++) d[a][b][c] = 0.f;

    auto load_tile = [&](int buf, int k0) {
        float* As = sm + buf * SBUF2;
        float* Bs = As + 128 * AS_LD;
#pragma unroll
        for (int i = 0; i < 4; i++) {
            int f = i * 256 + tid, row = f >> 3, q = f & 7;
            cpa16(As + row * AS_LD + q * 4, A + (size_t)(m0 + row) * HID + k0 + q * 4);
        }
#pragma unroll
        for (int i = 0; i < 4; i++) {
            int f = i * 256 + tid, k = f >> 5, q = f & 31;
            cpa16(Bs + k * BS2_LD + q * 4, g_WoT + (k0 + k) * VOC + q * 4);
        }
    };

    load_tile(0, 0);
    CP_COMMIT();
    CP_WAIT(0);
    __syncthreads();

    for (int kt = 0; kt < 16; kt++) {
        if (kt < 15) { load_tile((kt + 1) & 1, (kt + 1) * 32); CP_COMMIT(); }
        const float* As = sm + (kt & 1) * SBUF2;
        const float* Bs = As + 128 * AS_LD;
#pragma unroll
        for (int ks = 0; ks < 4; ks++) {
            const int kk = ks * 8;
            unsigned a[2][4];
#pragma unroll
            for (int mf = 0; mf < 2; mf++) {
                int r = wm + mf * 16 + q2;
                a[mf][0] = __float_as_uint(As[r * AS_LD + kk + l3]);
                a[mf][1] = __float_as_uint(As[(r + 8) * AS_LD + kk + l3]);
                a[mf][2] = __float_as_uint(As[r * AS_LD + kk + 4 + l3]);
                a[mf][3] = __float_as_uint(As[(r + 8) * AS_LD + kk + 4 + l3]);
            }
#pragma unroll
            for (int nf = 0; nf < 8; nf++) {
                int col = wn + nf * 8 + q2;
                unsigned b0 = __float_as_uint(Bs[(kk + l3) * BS2_LD + col]);
                unsigned b1 = __float_as_uint(Bs[(kk + 4 + l3) * BS2_LD + col]);
                mma8(d[0][nf], a[0], b0, b1);
                mma8(d[1][nf], a[1], b0, b1);
            }
        }
        if (kt < 15) { CP_WAIT(0); __syncthreads(); }
    }

    __syncthreads();

#pragma unroll
    for (int mf = 0; mf < 2; mf++)
#pragma unroll
        for (int nf = 0; nf < 8; nf++)
#pragma unroll
            for (int rh = 0; rh < 2; rh++) {
                int r = wm + mf * 16 + q2 + rh * 8;
                int col = wn + nf * 8 + l3 * 2;
                *reinterpret_cast<float2*>(ep + r * EP_LD + col) =
                    make_float2(d[mf][nf][rh * 2], d[mf][nf][rh * 2 + 1]);
            }
    __syncthreads();

    for (int i = 0; i < 16; i++) {
        int row = w * 16 + i;
        float x[4];
        float mx = -1e30f;
#pragma unroll
        for (int q = 0; q < 4; q++) {
            int v = lane + q * 32;
            x[q] = ep[row * EP_LD + v] + bout[v];
            mx = fmaxf(mx, x[q]);
        }
#pragma unroll
        for (int off = 16; off > 0; off >>= 1)
            mx = fmaxf(mx, __shfl_xor_sync(0xffffffffu, mx, off));
        float s = 0.f;
#pragma unroll
        for (int q = 0; q < 4; q++) s += expf(x[q] - mx);
#pragma unroll
        for (int off = 16; off > 0; off >>= 1)
            s += __shfl_xor_sync(0xffffffffu, s, off);
        float L = mx + logf(s);
        float* orow = out + (size_t)(m0 + row) * VOC;
#pragma unroll
        for (int q = 0; q < 4; q++) orow[lane + q * 32] = x[q] - L;
    }
}

__global__ void finalize_h(float* __restrict__ out) {
    float* dst = out + (size_t)TLEN * BSZ * VOC;
    for (int i = blockIdx.x * blockDim.x + threadIdx.x; i < BSZ * HID;
         i += gridDim.x * blockDim.x)
        dst[i] = g_H[0][i];   // after t=159: nxt = 0
}

// ---------------------------------------------------------------------------
extern "C" void kernel_launch(void* const* d_in, const int* in_sizes, int n_in,
                              void* d_out, int out_size) {
    (void)in_sizes; (void)n_in; (void)out_size;
    const float* enc_h = (const float*)d_in[1];
    const int*   tgt   = (const int*)d_in[2];
    const float* emb   = (const float*)d_in[3];
    const float* Wih   = (const float*)d_in[4];
    const float* Whh   = (const float*)d_in[5];
    const float* bih   = (const float*)d_in[6];
    const float* bhh   = (const float*)d_in[7];
    const float* Wout  = (const float*)d_in[8];
    const float* bout  = (const float*)d_in[9];
    float* out = (float*)d_out;

    const int gru_smem = NSTAGE * SBUF * 4;   // 95232 B (x2 CTAs = 190 KB/SM)
    const int log_smem = 2 * SBUF2 * 4;       // 71680 B
    cudaFuncSetAttribute(gru_step,   cudaFuncAttributeMaxDynamicSharedMemorySize, gru_smem);
    cudaFuncSetAttribute(logits_all, cudaFuncAttributeMaxDynamicSharedMemorySize, log_smem);

    prep_w <<<512, 256>>>(Whh, Wout);
    prep_gi<<<VOC, 256>>>(emb, Wih, bih);
    init_h <<<1024, 256>>>(enc_h);

    for (int t = 0; t < TLEN; t++)
        gru_step<<<dim3(16, 16), 256, gru_smem>>>(t, tgt, bhh);

    logits_all<<<(TLEN * BSZ) / 128, 256, log_smem>>>(bout, out);
    finalize_h<<<1024, 256>>>(out);
}

// round 12
// speedup vs baseline: 1.4779x; 1.3883x over previous
#include <cuda_runtime.h>
#include <cuda_bf16.h>
#include <cmath>

// ---------------------------------------------------------------------------
// DecoderRNN (mma.sync; tcgen05 unavailable on this ptxas target):
//  * gi table precompute (token -> 1536 gate inputs)
//  * per-step fused GEMM+GRU: bf16 m16n8k16 mma (fp32 accum; gate math fp32),
//    3-stage cp.async, 256 CTAs x 256 thr (2/SM), warp tile 32x48,
//    register GRU epilogue. h carried in fp32; bf16 copy feeds next GEMM,
//    tf32 copy feeds the (tf32) batched logits GEMM.
//  * ONE batched logits GEMM (tf32) + fused log_softmax at the end
// Output: [160*2048*128 log_probs fp32][2048*512 final hidden fp32]
// ---------------------------------------------------------------------------

#define HID   512
#define VOC   128
#define EMBD  64
#define BSZ   2048
#define TLEN  160
#define G3    1536

// gru bf16 tiling
#define A_LD   40      // bf16 units per A row (32 data + 8 pad = 80 B)
#define B_LD   40      // bf16 units per B col-row (K-contig)
#define SBUF_BF (128 * A_LD + 96 * B_LD)     // 8960 bf16 per stage (17.9 KB)
#define NSTAGE 3

// logits tf32 tiling (proven path, unchanged)
#define AS_LD  36
#define BS2_LD 136
#define EP_LD  132
#define SBUF2  (128 * AS_LD + 32 * BS2_LD)

// Static scratch
__device__ __nv_bfloat16 g_Wb [G3 * HID];                // W_hh bf16, [n][k]
__device__ float g_WoT [HID * VOC];                      // W_out^T tf32 [k][v]
__device__ float g_GI  [VOC * G3];                       // gi table (incl b_ih)
__device__ float g_H   [2][BSZ * HID];                   // fp32 hidden ping-pong
__device__ float g_Hall[(size_t)(TLEN + 1) * BSZ * HID]; // tf32 hidden (logits in)
__device__ __nv_bfloat16 g_Hab[(size_t)(TLEN + 1) * BSZ * HID]; // bf16 hidden (gru in)

__device__ __forceinline__ float tf32r(float x) {
    unsigned u;
    asm("cvt.rna.tf32.f32 %0, %1;" : "=r"(u) : "f"(x));
    return __uint_as_float(u);
}

__device__ __forceinline__ void cpa16(const void* dst, const void* src) {
    unsigned d = (unsigned)__cvta_generic_to_shared(dst);
    asm volatile("cp.async.cg.shared.global [%0], [%1], 16;" :: "r"(d), "l"(src));
}
#define CP_COMMIT() asm volatile("cp.async.commit_group;")
#define CP_WAIT(n)  asm volatile("cp.async.wait_group %0;" :: "n"(n))

__device__ __forceinline__ void mmabf(float d[4], const unsigned a[4],
                                      unsigned b0, unsigned b1) {
    asm volatile("mma.sync.aligned.m16n8k16.row.col.f32.bf16.bf16.f32 "
                 "{%0,%1,%2,%3}, {%4,%5,%6,%7}, {%8,%9}, {%0,%1,%2,%3};"
                 : "+f"(d[0]), "+f"(d[1]), "+f"(d[2]), "+f"(d[3])
                 : "r"(a[0]), "r"(a[1]), "r"(a[2]), "r"(a[3]), "r"(b0), "r"(b1));
}

__device__ __forceinline__ void mma8(float d[4], const unsigned a[4],
                                     unsigned b0, unsigned b1) {
    asm volatile("mma.sync.aligned.m16n8k8.row.col.f32.tf32.tf32.f32 "
                 "{%0,%1,%2,%3}, {%4,%5,%6,%7}, {%8,%9}, {%0,%1,%2,%3};"
                 : "+f"(d[0]), "+f"(d[1]), "+f"(d[2]), "+f"(d[3])
                 : "r"(a[0]), "r"(a[1]), "r"(a[2]), "r"(a[3]), "r"(b0), "r"(b1));
}

// ---------------------------------------------------------------------------
// Precompute
// ---------------------------------------------------------------------------
__global__ void prep_w(const float* __restrict__ Whh, const float* __restrict__ Wout) {
    const int n1 = G3 * HID, ntot = n1 + HID * VOC;
    for (int idx = blockIdx.x * blockDim.x + threadIdx.x; idx < ntot;
         idx += gridDim.x * blockDim.x) {
        if (idx < n1) {
            g_Wb[idx] = __float2bfloat16_rn(Whh[idx]);   // keep [n][k] layout
        } else {
            int j = idx - n1, v = j / HID, k = j % HID;
            g_WoT[k * VOC + v] = tf32r(Wout[j]);
        }
    }
}

__global__ void prep_gi(const float* __restrict__ emb, const float* __restrict__ Wih,
                        const float* __restrict__ bih) {
    __shared__ float x[EMBD];
    const int v = blockIdx.x;
    if (threadIdx.x < EMBD) x[threadIdx.x] = fmaxf(emb[v * EMBD + threadIdx.x], 0.f);
    __syncthreads();
    for (int n = threadIdx.x; n < G3; n += blockDim.x) {
        float acc = bih[n];
        const float* w = Wih + n * EMBD;
#pragma unroll
        for (int e = 0; e < EMBD; e++) acc += x[e] * w[e];
        g_GI[v * G3 + n] = acc;
    }
}

__global__ void init_h(const float* __restrict__ eh) {
    for (int i = blockIdx.x * blockDim.x + threadIdx.x; i < BSZ * HID;
         i += gridDim.x * blockDim.x) {
        float h = eh[i];
        g_H[0][i]  = h;
        g_Hall[i]  = tf32r(h);                  // slot 0 (logits input)
        g_Hab[i]   = __float2bfloat16_rn(h);    // slot 0 (gru input)
    }
}

// ---------------------------------------------------------------------------
// GRU step, bf16. Grid (16 j, 16 m) = 256 CTAs, 256 threads = 8 warps.
// CTA tile: 128 rows x 32 jj x 3 gates (N=96). Warps 4(M) x 2(N), 32x48 each.
// K-contiguous bf16 smem (80B rows, conflict-free), 3-stage cp.async.
// ---------------------------------------------------------------------------
__global__ void __launch_bounds__(256, 2)
gru_step(int t, const int* __restrict__ tgt, const float* __restrict__ bhh) {
    extern __shared__ __nv_bfloat16 smb[];

    const int tid  = threadIdx.x;
    const int lane = tid & 31, w = tid >> 5;
    const int l3 = lane & 3, q2 = lane >> 2;
    const int wm = (w >> 1) * 32;      // warp M offset (0,32,64,96)
    const int wn = (w & 1);            // warp N group (16 jj)
    const int m0 = blockIdx.y * 128;
    const int j0 = blockIdx.x * 32;

    const int cur = t & 1, nxt = cur ^ 1;
    const __nv_bfloat16* __restrict__ A = g_Hab + (size_t)t * BSZ * HID;

    float d[2][6][4];
#pragma unroll
    for (int a = 0; a < 2; a++)
#pragma unroll
        for (int b = 0; b < 6; b++)
#pragma unroll
            for (int c = 0; c < 4; c++) d[a][b][c] = 0.f;

    // ---- tile loader: A 128x32 bf16, B 96x32 bf16 (K-contig) ----
    auto load_tile = [&](int buf, int kt) {
        __nv_bfloat16* As = smb + buf * SBUF_BF;
        __nv_bfloat16* Bs = As + 128 * A_LD;
        const int k0 = kt * 32;
#pragma unroll
        for (int i = 0; i < 2; i++) {              // A: 128 rows x 4 chunks(16B)
            int f = i * 256 + tid, row = f >> 2, q = f & 3;
            cpa16(As + row * A_LD + q * 8,
                  A + (size_t)(m0 + row) * HID + k0 + q * 8);
        }
#pragma unroll
        for (int i = 0; i < 2; i++) {              // B: 96 cols x 4 chunks
            int f = i * 256 + tid;
            if (f < 384) {
                int col = f >> 2, q = f & 3;
                int blk = col / 48, rem = col % 48, g = rem >> 4, jjw = rem & 15;
                cpa16(Bs + col * B_LD + q * 8,
                      g_Wb + (size_t)(g * HID + j0 + blk * 16 + jjw) * HID + k0 + q * 8);
            }
        }
    };

    // ---- prologue: stages 0,1 in flight; stage 0 resident ----
    load_tile(0, 0); CP_COMMIT();
    load_tile(1, 1); CP_COMMIT();
    CP_WAIT(1);
    __syncthreads();

    for (int kt = 0; kt < 16; kt++) {
        const __nv_bfloat16* As = smb + (kt % NSTAGE) * SBUF_BF;
        const __nv_bfloat16* Bs = As + 128 * A_LD;
#pragma unroll
        for (int ks = 0; ks < 2; ks++) {           // two k16 groups per 32-K tile
            const int kb = ks * 16;
            unsigned a[2][4];
#pragma unroll
            for (int mf = 0; mf < 2; mf++) {
                int row = wm + mf * 16 + q2;
                a[mf][0] = *reinterpret_cast<const unsigned*>(As + row * A_LD + kb + 2 * l3);
                a[mf][1] = *reinterpret_cast<const unsigned*>(As + (row + 8) * A_LD + kb + 2 * l3);
                a[mf][2] = *reinterpret_cast<const unsigned*>(As + row * A_LD + kb + 2 * l3 + 8);
                a[mf][3] = *reinterpret_cast<const unsigned*>(As + (row + 8) * A_LD + kb + 2 * l3 + 8);
            }
#pragma unroll
            for (int nf = 0; nf < 6; nf++) {
                int col = wn * 48 + nf * 8 + q2;
                unsigned b0 = *reinterpret_cast<const unsigned*>(Bs + col * B_LD + kb + 2 * l3);
                unsigned b1 = *reinterpret_cast<const unsigned*>(Bs + col * B_LD + kb + 2 * l3 + 8);
                mmabf(d[0][nf], a[0], b0, b1);
                mmabf(d[1][nf], a[1], b0, b1);
            }
        }
        if (kt < 15) {
            if (kt + 2 < 16) {
                load_tile((kt + 2) % NSTAGE, kt + 2); CP_COMMIT();
                CP_WAIT(1);                         // tile kt+1 resident
            } else {
                CP_WAIT(0);
            }
            __syncthreads();
        }
    }

    // ---- register GRU epilogue (fp32 math) ----
    const float* __restrict__ Hc = g_H[cur];
    float* __restrict__ Hn  = g_H[nxt];
    float* __restrict__ Ha  = g_Hall + (size_t)(t + 1) * BSZ * HID;
    __nv_bfloat16* __restrict__ Hb = g_Hab + (size_t)(t + 1) * BSZ * HID;
#pragma unroll
    for (int mf = 0; mf < 2; mf++) {
#pragma unroll
        for (int rh = 0; rh < 2; rh++) {
            const int row = m0 + wm + mf * 16 + q2 + rh * 8;
            const int tok = (t == 0) ? 0 : __ldg(tgt + row * TLEN + t - 1);
            const float* __restrict__ gi = g_GI + tok * G3;
#pragma unroll
            for (int jf = 0; jf < 2; jf++) {
                const int j2 = j0 + wn * 16 + jf * 8 + l3 * 2;
                float h[2];
#pragma unroll
                for (int p = 0; p < 2; p++) {
                    const int r = rh * 2 + p;
                    const int j = j2 + p;
                    float gr  = d[mf][jf][r]     + bhh[j]         + gi[j];
                    float gz  = d[mf][2 + jf][r] + bhh[HID + j]   + gi[HID + j];
                    float ghn = d[mf][4 + jf][r] + bhh[2*HID + j];
                    float rr = 1.f / (1.f + expf(-gr));
                    float zz = 1.f / (1.f + expf(-gz));
                    float nn = tanhf(gi[2*HID + j] + rr * ghn);
                    float ho = Hc[(size_t)row * HID + j];
                    h[p] = fmaf(zz, ho - nn, nn);   // (1-z)n + z*ho
                }
                *reinterpret_cast<float2*>(Hn + (size_t)row * HID + j2) =
                    make_float2(h[0], h[1]);
                *reinterpret_cast<float2*>(Ha + (size_t)row * HID + j2) =
                    make_float2(tf32r(h[0]), tf32r(h[1]));
                *reinterpret_cast<__nv_bfloat162*>(Hb + (size_t)row * HID + j2) =
                    __floats2bfloat162_rn(h[0], h[1]);
            }
        }
    }
}

// ---------------------------------------------------------------------------
// Batched logits (tf32, proven): (160*2048) x 128 x 512 GEMM + log_softmax.
// ---------------------------------------------------------------------------
__global__ void __launch_bounds__(256, 1)
logits_all(const float* __restrict__ bout, float* __restrict__ out) {
    extern __shared__ float sm[];
    float* ep = sm;

    const int tid = threadIdx.x, lane = tid & 31, w = tid >> 5;
    const int l3 = lane & 3, q2 = lane >> 2;
    const int wm = (w >> 1) * 32, wn = (w & 1) * 64;
    const int m0 = blockIdx.x * 128;

    const float* __restrict__ A = g_Hall + (size_t)BSZ * HID;   // slots 1..160

    float d[2][8][4];
#pragma unroll
    for (int a = 0; a < 2; a++)
#pragma unroll
        for (int b = 0; b < 8; b++)
#pragma unroll
            for (int c = 0; c < 4; c++) d[a][b][c] = 0.f;

    auto load_tile = [&](int buf, int k0) {
        float* As = sm + buf * SBUF2;
        float* Bs = As + 128 * AS_LD;
#pragma unroll
        for (int i = 0; i < 4; i++) {
            int f = i * 256 + tid, row = f >> 3, q = f & 7;
            cpa16(As + row * AS_LD + q * 4, A + (size_t)(m0 + row) * HID + k0 + q * 4);
        }
#pragma unroll
        for (int i = 0; i < 4; i++) {
            int f = i * 256 + tid, k = f >> 5, q = f & 31;
            cpa16(Bs + k * BS2_LD + q * 4, g_WoT + (k0 + k) * VOC + q * 4);
        }
    };

    load_tile(0, 0);
    CP_COMMIT();
    CP_WAIT(0);
    __syncthreads();

    for (int kt = 0; kt < 16; kt++) {
        if (kt < 15) { load_tile((kt + 1) & 1, (kt + 1) * 32); CP_COMMIT(); }
        const float* As = sm + (kt & 1) * SBUF2;
        const float* Bs = As + 128 * AS_LD;
#pragma unroll
        for (int ks = 0; ks < 4; ks++) {
            const int kk = ks * 8;
            unsigned a[2][4];
#pragma unroll
            for (int mf = 0; mf < 2; mf++) {
                int r = wm + mf * 16 + q2;
                a[mf][0] = __float_as_uint(As[r * AS_LD + kk + l3]);
                a[mf][1] = __float_as_uint(As[(r + 8) * AS_LD + kk + l3]);
                a[mf][2] = __float_as_uint(As[r * AS_LD + kk + 4 + l3]);
                a[mf][3] = __float_as_uint(As[(r + 8) * AS_LD + kk + 4 + l3]);
            }
#pragma unroll
            for (int nf = 0; nf < 8; nf++) {
                int col = wn + nf * 8 + q2;
                unsigned b0 = __float_as_uint(Bs[(kk + l3) * BS2_LD + col]);
                unsigned b1 = __float_as_uint(Bs[(kk + 4 + l3) * BS2_LD + col]);
                mma8(d[0][nf], a[0], b0, b1);
                mma8(d[1][nf], a[1], b0, b1);
            }
        }
        if (kt < 15) { CP_WAIT(0); __syncthreads(); }
    }

    __syncthreads();

#pragma unroll
    for (int mf = 0; mf < 2; mf++)
#pragma unroll
        for (int nf = 0; nf < 8; nf++)
#pragma unroll
            for (int rh = 0; rh < 2; rh++) {
                int r = wm + mf * 16 + q2 + rh * 8;
                int col = wn + nf * 8 + l3 * 2;
                *reinterpret_cast<float2*>(ep + r * EP_LD + col) =
                    make_float2(d[mf][nf][rh * 2], d[mf][nf][rh * 2 + 1]);
            }
    __syncthreads();

    for (int i = 0; i < 16; i++) {
        int row = w * 16 + i;
        float x[4];
        float mx = -1e30f;
#pragma unroll
        for (int q = 0; q < 4; q++) {
            int v = lane + q * 32;
            x[q] = ep[row * EP_LD + v] + bout[v];
            mx = fmaxf(mx, x[q]);
        }
#pragma unroll
        for (int off = 16; off > 0; off >>= 1)
            mx = fmaxf(mx, __shfl_xor_sync(0xffffffffu, mx, off));
        float s = 0.f;
#pragma unroll
        for (int q = 0; q < 4; q++) s += expf(x[q] - mx);
#pragma unroll
        for (int off = 16; off > 0; off >>= 1)
            s += __shfl_xor_sync(0xffffffffu, s, off);
        float L = mx + logf(s);
        float* orow = out + (size_t)(m0 + row) * VOC;
#pragma unroll
        for (int q = 0; q < 4; q++) orow[lane + q * 32] = x[q] - L;
    }
}

__global__ void finalize_h(float* __restrict__ out) {
    float* dst = out + (size_t)TLEN * BSZ * VOC;
    for (int i = blockIdx.x * blockDim.x + threadIdx.x; i < BSZ * HID;
         i += gridDim.x * blockDim.x)
        dst[i] = g_H[0][i];   // after t=159: nxt = 0
}

// ---------------------------------------------------------------------------
extern "C" void kernel_launch(void* const* d_in, const int* in_sizes, int n_in,
                              void* d_out, int out_size) {
    (void)in_sizes; (void)n_in; (void)out_size;
    const float* enc_h = (const float*)d_in[1];
    const int*   tgt   = (const int*)d_in[2];
    const float* emb   = (const float*)d_in[3];
    const float* Wih   = (const float*)d_in[4];
    const float* Whh   = (const float*)d_in[5];
    const float* bih   = (const float*)d_in[6];
    const float* bhh   = (const float*)d_in[7];
    const float* Wout  = (const float*)d_in[8];
    const float* bout  = (const float*)d_in[9];
    float* out = (float*)d_out;

    const int gru_smem = NSTAGE * SBUF_BF * 2;   // 53760 B (x2 CTAs/SM)
    const int log_smem = 2 * SBUF2 * 4;          // 71680 B
    cudaFuncSetAttribute(gru_step,   cudaFuncAttributeMaxDynamicSharedMemorySize, gru_smem);
    cudaFuncSetAttribute(logits_all, cudaFuncAttributeMaxDynamicSharedMemorySize, log_smem);

    prep_w <<<512, 256>>>(Whh, Wout);
    prep_gi<<<VOC, 256>>>(emb, Wih, bih);
    init_h <<<1024, 256>>>(enc_h);

    for (int t = 0; t < TLEN; t++)
        gru_step<<<dim3(16, 16), 256, gru_smem>>>(t, tgt, bhh);

    logits_all<<<(TLEN * BSZ) / 128, 256, log_smem>>>(bout, out);
    finalize_h<<<1024, 256>>>(out);
}

// round 13
// speedup vs baseline: 1.8214x; 1.2324x over previous
#include <cuda_runtime.h>
#include <cuda_bf16.h>
#include <cstdint>
#include <cmath>

// ---------------------------------------------------------------------------
// DecoderRNN (mma.sync bf16; loads via cp.async.bulk):
//  * R12 was cp.async-ISSUE-bound (~3.5M 16B cp.asyncs/step). This round keeps
//    the exact R12 MMA/fragment structure but loads each smem tile with ONE
//    cp.async.bulk (UBLKCP) from tile-contiguous gmem staging:
//      - hidden states written by the epilogue in tiled layout
//        g_Hab[t][mtile][ktile][128 rows][40 bf16]  (10240 B blocks)
//      - weights staged tiled by prep_w: g_Wst[jtile][ktile][96 cols][40 bf16]
//  * 3-stage mbarrier ring, 256 CTAs x 256 thr (2/SM), warp tile 32x48.
//  * gates fp32 (+fast exp); h fp32; bf16 tiled copy feeds next GEMM; tf32
//    copy feeds the batched tf32 logits GEMM + fused log_softmax at the end.
// Output: [160*2048*128 log_probs fp32][2048*512 final hidden fp32]
// ---------------------------------------------------------------------------

#define HID   512
#define VOC   128
#define EMBD  64
#define BSZ   2048
#define TLEN  160
#define G3    1536

// gru bf16 tiling (tiled blocks, 40-bf16 row stride: 64B data + 16B pad)
#define ABLK   (128 * 40)            // 5120 bf16 = 10240 B per A block
#define BBLK   (96 * 40)             // 3840 bf16 =  7680 B per B block
#define STAGE_BYTES (10240 + 7680)   // 17920 B per pipeline stage
#define NSTAGE 3

// logits tf32 tiling (proven path, unchanged)
#define AS_LD  36
#define BS2_LD 136
#define EP_LD  132
#define SBUF2  (128 * AS_LD + 32 * BS2_LD)

// Static scratch
__device__ __nv_bfloat16 g_Wst[16 * 16 * BBLK];          // W_hh bf16, tiled
__device__ float g_WoT [HID * VOC];                      // W_out^T tf32 [k][v]
__device__ float g_GI  [VOC * G3];                       // gi table (incl b_ih)
__device__ float g_H   [2][BSZ * HID];                   // fp32 hidden ping-pong
__device__ float g_Hall[(size_t)(TLEN + 1) * BSZ * HID]; // tf32 hidden (logits in)
__device__ __nv_bfloat16 g_Hab[(size_t)(TLEN + 1) * 256 * ABLK]; // bf16 tiled hidden

__device__ __forceinline__ float tf32r(float x) {
    unsigned u;
    asm("cvt.rna.tf32.f32 %0, %1;" : "=r"(u) : "f"(x));
    return __uint_as_float(u);
}
__device__ __forceinline__ uint32_t smem_u32(const void* p) {
    uint32_t a;
    asm("{ .reg .u64 t; cvta.to.shared.u64 t, %1; cvt.u32.u64 %0, t; }" : "=r"(a) : "l"(p));
    return a;
}
__device__ __forceinline__ void cpa16(const void* dst, const void* src) {
    unsigned d = (unsigned)__cvta_generic_to_shared(dst);
    asm volatile("cp.async.cg.shared.global [%0], [%1], 16;" :: "r"(d), "l"(src));
}
#define CP_COMMIT() asm volatile("cp.async.commit_group;")
#define CP_WAIT(n)  asm volatile("cp.async.wait_group %0;" :: "n"(n))

__device__ __forceinline__ void mb_init(uint32_t a, uint32_t cnt) {
    asm volatile("mbarrier.init.shared.b64 [%0], %1;" :: "r"(a), "r"(cnt) : "memory");
}
__device__ __forceinline__ void mb_wait(uint32_t a, uint32_t parity) {
    asm volatile(
        "{\n\t.reg .pred P;\n\t"
        "W_%=:\n\t"
        "mbarrier.try_wait.parity.acquire.cta.shared::cta.b64 P, [%0], %1, 0x989680;\n\t"
        "@P bra.uni D_%=;\n\t"
        "bra.uni W_%=;\n\t"
        "D_%=:\n\t}"
        :: "r"(a), "r"(parity) : "memory");
}
__device__ __forceinline__ void mb_expect(uint32_t a, uint32_t bytes) {
    asm volatile("mbarrier.arrive.expect_tx.shared.b64 _, [%0], %1;"
                 :: "r"(a), "r"(bytes) : "memory");
}
__device__ __forceinline__ void bulk_g2s(uint32_t dst, const void* src,
                                         uint32_t bytes, uint32_t mbar) {
    asm volatile("cp.async.bulk.shared::cta.global.mbarrier::complete_tx::bytes "
                 "[%0], [%1], %2, [%3];"
                 :: "r"(dst), "l"(src), "r"(bytes), "r"(mbar) : "memory");
}

__device__ __forceinline__ void mmabf(float d[4], const unsigned a[4],
                                      unsigned b0, unsigned b1) {
    asm volatile("mma.sync.aligned.m16n8k16.row.col.f32.bf16.bf16.f32 "
                 "{%0,%1,%2,%3}, {%4,%5,%6,%7}, {%8,%9}, {%0,%1,%2,%3};"
                 : "+f"(d[0]), "+f"(d[1]), "+f"(d[2]), "+f"(d[3])
                 : "r"(a[0]), "r"(a[1]), "r"(a[2]), "r"(a[3]), "r"(b0), "r"(b1));
}
__device__ __forceinline__ void mma8(float d[4], const unsigned a[4],
                                     unsigned b0, unsigned b1) {
    asm volatile("mma.sync.aligned.m16n8k8.row.col.f32.tf32.tf32.f32 "
                 "{%0,%1,%2,%3}, {%4,%5,%6,%7}, {%8,%9}, {%0,%1,%2,%3};"
                 : "+f"(d[0]), "+f"(d[1]), "+f"(d[2]), "+f"(d[3])
                 : "r"(a[0]), "r"(a[1]), "r"(a[2]), "r"(a[3]), "r"(b0), "r"(b1));
}

__device__ __forceinline__ float sigf(float x) {
    return __fdividef(1.f, 1.f + __expf(-x));
}
__device__ __forceinline__ float tanhfast(float x) {
    return 1.f - __fdividef(2.f, __expf(2.f * x) + 1.f);
}

// ---------------------------------------------------------------------------
// Precompute
// ---------------------------------------------------------------------------
__global__ void prep_w(const float* __restrict__ Whh, const float* __restrict__ Wout) {
    const int nB = 16 * 16 * 96 * 32;               // tiled W elements
    const int ntot = nB + HID * VOC;
    for (int idx = blockIdx.x * blockDim.x + threadIdx.x; idx < ntot;
         idx += gridDim.x * blockDim.x) {
        if (idx < nB) {
            int kk  = idx & 31;
            int c   = (idx >> 5) % 96;
            int rest= (idx >> 5) / 96;               // 0..255
            int ktl = rest & 15, jt = rest >> 4;
            int blk = c / 48, r48 = c % 48;
            int g = r48 >> 4, jjw = r48 & 15;
            int n = g * HID + jt * 32 + blk * 16 + jjw;
            int k = ktl * 32 + kk;
            g_Wst[((size_t)(jt * 16 + ktl) * 96 + c) * 40 + kk] =
                __float2bfloat16_rn(Whh[(size_t)n * HID + k]);
        } else {
            int j = idx - nB, v = j / HID, k = j % HID;
            g_WoT[k * VOC + v] = tf32r(Wout[j]);
        }
    }
}

__global__ void prep_gi(const float* __restrict__ emb, const float* __restrict__ Wih,
                        const float* __restrict__ bih) {
    __shared__ float x[EMBD];
    const int v = blockIdx.x;
    if (threadIdx.x < EMBD) x[threadIdx.x] = fmaxf(emb[v * EMBD + threadIdx.x], 0.f);
    __syncthreads();
    for (int n = threadIdx.x; n < G3; n += blockDim.x) {
        float acc = bih[n];
        const float* w = Wih + n * EMBD;
#pragma unroll
        for (int e = 0; e < EMBD; e++) acc += x[e] * w[e];
        g_GI[v * G3 + n] = acc;
    }
}

__global__ void init_h(const float* __restrict__ eh) {
    for (int i = blockIdx.x * blockDim.x + threadIdx.x; i < BSZ * HID;
         i += gridDim.x * blockDim.x) {
        float h = eh[i];
        int b = i >> 9, k = i & 511;
        g_H[0][i]  = h;
        g_Hall[i]  = tf32r(h);
        g_Hab[((size_t)(b >> 7) * 16 + (k >> 5)) * ABLK
              + (size_t)(b & 127) * 40 + (k & 31)] = __float2bfloat16_rn(h);
    }
}

// ---------------------------------------------------------------------------
// GRU step. Grid (16 j, 16 m) = 256 CTAs, 256 threads, 2 CTAs/SM.
// Per K-tile: 2 cp.async.bulk (A 10240B + B 7680B) into a 3-stage mbarrier
// ring. Warps 4(M) x 2(N), warp tile 32x48; fragment indices as in R12.
// ---------------------------------------------------------------------------
__global__ void __launch_bounds__(256, 2)
gru_step(int t, const int* __restrict__ tgt, const float* __restrict__ bhh) {
    extern __shared__ __align__(128) unsigned char smraw[];
    __shared__ __align__(8) unsigned long long s_mb[NSTAGE];

    const int tid  = threadIdx.x;
    const int lane = tid & 31, w = tid >> 5;
    const int l3 = lane & 3, q2 = lane >> 2;
    const int wm = (w >> 1) * 32;      // warp M offset (0,32,64,96)
    const int wn = (w & 1);            // warp N group (16 jj)
    const int m0 = blockIdx.y * 128;
    const int j0 = blockIdx.x * 32;
    const int cur = t & 1, nxt = cur ^ 1;

    const uint32_t sb = smem_u32(smraw);
    uint32_t mb[NSTAGE];
#pragma unroll
    for (int s = 0; s < NSTAGE; s++) mb[s] = smem_u32(&s_mb[s]);

    if (tid == 0) {
#pragma unroll
        for (int s = 0; s < NSTAGE; s++) mb_init(mb[s], 1);
    }
    __syncthreads();

    const __nv_bfloat16* __restrict__ Asrc =
        g_Hab + ((size_t)t * 256 + (size_t)blockIdx.y * 16) * ABLK;
    const __nv_bfloat16* __restrict__ Bsrc =
        g_Wst + (size_t)blockIdx.x * 16 * BBLK;

    auto issue = [&](int kt) {
        const int s = kt % NSTAGE;
        const uint32_t as = sb + s * STAGE_BYTES;
        mb_expect(mb[s], STAGE_BYTES);
        bulk_g2s(as,         Asrc + (size_t)kt * ABLK, 10240u, mb[s]);
        bulk_g2s(as + 10240, Bsrc + (size_t)kt * BBLK,  7680u, mb[s]);
    };

    if (tid == 0) { issue(0); issue(1); }

    float d[2][6][4];
#pragma unroll
    for (int a = 0; a < 2; a++)
#pragma unroll
        for (int b = 0; b < 6; b++)
#pragma unroll
            for (int c = 0; c < 4; c++) d[a][b][c] = 0.f;

    for (int kt = 0; kt < 16; kt++) {
        if (tid == 0 && kt < 14) issue(kt + 2);     // stage (kt+2)%3 freed by
                                                    // syncthreads at end of kt-1
        mb_wait(mb[kt % NSTAGE], (kt / NSTAGE) & 1);

        const __nv_bfloat16* As =
            reinterpret_cast<const __nv_bfloat16*>(smraw + (kt % NSTAGE) * STAGE_BYTES);
        const __nv_bfloat16* Bs = As + ABLK;        // +5120 bf16
#pragma unroll
        for (int ks = 0; ks < 2; ks++) {            // two k16 groups per tile
            const int kb = ks * 16;
            unsigned a[2][4];
#pragma unroll
            for (int mf = 0; mf < 2; mf++) {
                int row = wm + mf * 16 + q2;
                a[mf][0] = *reinterpret_cast<const unsigned*>(As + row * 40 + kb + 2 * l3);
                a[mf][1] = *reinterpret_cast<const unsigned*>(As + (row + 8) * 40 + kb + 2 * l3);
                a[mf][2] = *reinterpret_cast<const unsigned*>(As + row * 40 + kb + 2 * l3 + 8);
                a[mf][3] = *reinterpret_cast<const unsigned*>(As + (row + 8) * 40 + kb + 2 * l3 + 8);
            }
#pragma unroll
            for (int nf = 0; nf < 6; nf++) {
                int col = wn * 48 + nf * 8 + q2;
                unsigned b0 = *reinterpret_cast<const unsigned*>(Bs + col * 40 + kb + 2 * l3);
                unsigned b1 = *reinterpret_cast<const unsigned*>(Bs + col * 40 + kb + 2 * l3 + 8);
                mmabf(d[0][nf], a[0], b0, b1);
                mmabf(d[1][nf], a[1], b0, b1);
            }
        }
        if (kt < 15) __syncthreads();               // release stage kt%3 for reuse
    }

    // ---- register GRU epilogue (fp32 math, fast exp) ----
    const float* __restrict__ Hc = g_H[cur];
    float* __restrict__ Hn  = g_H[nxt];
    float* __restrict__ Ha  = g_Hall + (size_t)(t + 1) * BSZ * HID;
    __nv_bfloat16* __restrict__ Hb =
        g_Hab + ((size_t)(t + 1) * 256 + (size_t)blockIdx.y * 16 + blockIdx.x) * ABLK;
#pragma unroll
    for (int mf = 0; mf < 2; mf++) {
#pragma unroll
        for (int rh = 0; rh < 2; rh++) {
            const int lrow = wm + mf * 16 + q2 + rh * 8;
            const int row  = m0 + lrow;
            const int tok = (t == 0) ? 0 : __ldg(tgt + row * TLEN + t - 1);
            const float* __restrict__ gi = g_GI + tok * G3;
#pragma unroll
            for (int jf = 0; jf < 2; jf++) {
                const int lcol = wn * 16 + jf * 8 + l3 * 2;
                const int j2 = j0 + lcol;
                float h[2];
#pragma unroll
                for (int p = 0; p < 2; p++) {
                    const int r = rh * 2 + p;
                    const int j = j2 + p;
                    float gr  = d[mf][jf][r]     + bhh[j]         + gi[j];
                    float gz  = d[mf][2 + jf][r] + bhh[HID + j]   + gi[HID + j];
                    float ghn = d[mf][4 + jf][r] + bhh[2*HID + j];
                    float rr = sigf(gr);
                    float zz = sigf(gz);
                    float nn = tanhfast(gi[2*HID + j] + rr * ghn);
                    float ho = Hc[(size_t)row * HID + j];
                    h[p] = fmaf(zz, ho - nn, nn);   // (1-z)n + z*ho
                }
                *reinterpret_cast<float2*>(Hn + (size_t)row * HID + j2) =
                    make_float2(h[0], h[1]);
                *reinterpret_cast<float2*>(Ha + (size_t)row * HID + j2) =
                    make_float2(tf32r(h[0]), tf32r(h[1]));
                *reinterpret_cast<__nv_bfloat162*>(Hb + (size_t)lrow * 40 + lcol) =
                    __floats2bfloat162_rn(h[0], h[1]);
            }
        }
    }
}

// ---------------------------------------------------------------------------
// Batched logits (tf32, proven): (160*2048) x 128 x 512 GEMM + log_softmax.
// ---------------------------------------------------------------------------
__global__ void __launch_bounds__(256, 1)
logits_all(const float* __restrict__ bout, float* __restrict__ out) {
    extern __shared__ float sm[];
    float* ep = sm;

    const int tid = threadIdx.x, lane = tid & 31, w = tid >> 5;
    const int l3 = lane & 3, q2 = lane >> 2;
    const int wm = (w >> 1) * 32, wn = (w & 1) * 64;
    const int m0 = blockIdx.x * 128;

    const float* __restrict__ A = g_Hall + (size_t)BSZ * HID;   // slots 1..160

    float d[2][8][4];
#pragma unroll
    for (int a = 0; a < 2; a++)
#pragma unroll
        for (int b = 0; b < 8; b++)
#pragma unroll
            for (int c = 0; c < 4; c++) d[a][b][c] = 0.f;

    auto load_tile = [&](int buf, int k0) {
        float* As = sm + buf * SBUF2;
        float* Bs = As + 128 * AS_LD;
#pragma unroll
        for (int i = 0; i < 4; i++) {
            int f = i * 256 + tid, row = f >> 3, q = f & 7;
            cpa16(As + row * AS_LD + q * 4, A + (size_t)(m0 + row) * HID + k0 + q * 4);
        }
#pragma unroll
        for (int i = 0; i < 4; i++) {
            int f = i * 256 + tid, k = f >> 5, q = f & 31;
            cpa16(Bs + k * BS2_LD + q * 4, g_WoT + (k0 + k) * VOC + q * 4);
        }
    };

    load_tile(0, 0);
    CP_COMMIT();
    CP_WAIT(0);
    __syncthreads();

    for (int kt = 0; kt < 16; kt++) {
        if (kt < 15) { load_tile((kt + 1) & 1, (kt + 1) * 32); CP_COMMIT(); }
        const float* As = sm + (kt & 1) * SBUF2;
        const float* Bs = As + 128 * AS_LD;
#pragma unroll
        for (int ks = 0; ks < 4; ks++) {
            const int kk = ks * 8;
            unsigned a[2][4];
#pragma unroll
            for (int mf = 0; mf < 2; mf++) {
                int r = wm + mf * 16 + q2;
                a[mf][0] = __float_as_uint(As[r * AS_LD + kk + l3]);
                a[mf][1] = __float_as_uint(As[(r + 8) * AS_LD + kk + l3]);
                a[mf][2] = __float_as_uint(As[r * AS_LD + kk + 4 + l3]);
                a[mf][3] = __float_as_uint(As[(r + 8) * AS_LD + kk + 4 + l3]);
            }
#pragma unroll
            for (int nf = 0; nf < 8; nf++) {
                int col = wn + nf * 8 + q2;
                unsigned b0 = __float_as_uint(Bs[(kk + l3) * BS2_LD + col]);
                unsigned b1 = __float_as_uint(Bs[(kk + 4 + l3) * BS2_LD + col]);
                mma8(d[0][nf], a[0], b0, b1);
                mma8(d[1][nf], a[1], b0, b1);
            }
        }
        if (kt < 15) { CP_WAIT(0); __syncthreads(); }
    }

    __syncthreads();

#pragma unroll
    for (int mf = 0; mf < 2; mf++)
#pragma unroll
        for (int nf = 0; nf < 8; nf++)
#pragma unroll
            for (int rh = 0; rh < 2; rh++) {
                int r = wm + mf * 16 + q2 + rh * 8;
                int col = wn + nf * 8 + l3 * 2;
                *reinterpret_cast<float2*>(ep + r * EP_LD + col) =
                    make_float2(d[mf][nf][rh * 2], d[mf][nf][rh * 2 + 1]);
            }
    __syncthreads();

    for (int i = 0; i < 16; i++) {
        int row = w * 16 + i;
        float x[4];
        float mx = -1e30f;
#pragma unroll
        for (int q = 0; q < 4; q++) {
            int v = lane + q * 32;
            x[q] = ep[row * EP_LD + v] + bout[v];
            mx = fmaxf(mx, x[q]);
        }
#pragma unroll
        for (int off = 16; off > 0; off >>= 1)
            mx = fmaxf(mx, __shfl_xor_sync(0xffffffffu, mx, off));
        float s = 0.f;
#pragma unroll
        for (int q = 0; q < 4; q++) s += expf(x[q] - mx);
#pragma unroll
        for (int off = 16; off > 0; off >>= 1)
            s += __shfl_xor_sync(0xffffffffu, s, off);
        float L = mx + logf(s);
        float* orow = out + (size_t)(m0 + row) * VOC;
#pragma unroll
        for (int q = 0; q < 4; q++) orow[lane + q * 32] = x[q] - L;
    }
}

__global__ void finalize_h(float* __restrict__ out) {
    float* dst = out + (size_t)TLEN * BSZ * VOC;
    for (int i = blockIdx.x * blockDim.x + threadIdx.x; i < BSZ * HID;
         i += gridDim.x * blockDim.x)
        dst[i] = g_H[0][i];   // after t=159: nxt = 0
}

// ---------------------------------------------------------------------------
extern "C" void kernel_launch(void* const* d_in, const int* in_sizes, int n_in,
                              void* d_out, int out_size) {
    (void)in_sizes; (void)n_in; (void)out_size;
    const float* enc_h = (const float*)d_in[1];
    const int*   tgt   = (const int*)d_in[2];
    const float* emb   = (const float*)d_in[3];
    const float* Wih   = (const float*)d_in[4];
    const float* Whh   = (const float*)d_in[5];
    const float* bih   = (const float*)d_in[6];
    const float* bhh   = (const float*)d_in[7];
    const float* Wout  = (const float*)d_in[8];
    const float* bout  = (const float*)d_in[9];
    float* out = (float*)d_out;

    const int gru_smem = NSTAGE * STAGE_BYTES;   // 53760 B (x2 CTAs/SM)
    const int log_smem = 2 * SBUF2 * 4;          // 71680 B
    cudaFuncSetAttribute(gru_step,   cudaFuncAttributeMaxDynamicSharedMemorySize, gru_smem);
    cudaFuncSetAttribute(logits_all, cudaFuncAttributeMaxDynamicSharedMemorySize, log_smem);

    prep_w <<<512, 256>>>(Whh, Wout);
    prep_gi<<<VOC, 256>>>(emb, Wih, bih);
    init_h <<<1024, 256>>>(enc_h);

    for (int t = 0; t < TLEN; t++)
        gru_step<<<dim3(16, 16), 256, gru_smem>>>(t, tgt, bhh);

    logits_all<<<(TLEN * BSZ) / 128, 256, log_smem>>>(bout, out);
    finalize_h<<<1024, 256>>>(out);
}

// round 14
// speedup vs baseline: 2.0818x; 1.1430x over previous
#include <cuda_runtime.h>
#include <cuda_bf16.h>
#include <cstdint>
#include <cmath>

// ---------------------------------------------------------------------------
// DecoderRNN (mma.sync bf16 + cp.async.bulk + ldmatrix):
//  * R13 mainloop was LDS/issue-bound (40 scalar LDS + address ALU per K-tile
//    per warp). This round swaps fragment loads to ldmatrix.x4 (10 LDSM/tile)
//    with addresses precomputed per thread; 4-stage bulk-copy mbarrier ring.
//  * Tiled gmem staging as R13: A blocks written by the epilogue, W blocks by
//    prep_w; one cp.async.bulk per operand per K-tile.
//  * gates fp32 (+fast exp); h fp32; bf16 tiled copy feeds next GEMM; tf32
//    copy feeds the batched tf32 logits GEMM + fused log_softmax at the end.
// Output: [160*2048*128 log_probs fp32][2048*512 final hidden fp32]
// ---------------------------------------------------------------------------

#define HID   512
#define VOC   128
#define EMBD  64
#define BSZ   2048
#define TLEN  160
#define G3    1536

// gru bf16 tiling (tiled blocks, 40-bf16 row stride: 64B data + 16B pad)
#define ABLK   (128 * 40)            // 5120 bf16 = 10240 B per A block
#define BBLK   (96 * 40)             // 3840 bf16 =  7680 B per B block
#define STAGE_BYTES (10240 + 7680)   // 17920 B per pipeline stage
#define NSTAGE 4

// logits tf32 tiling (proven path, unchanged)
#define AS_LD  36
#define BS2_LD 136
#define EP_LD  132
#define SBUF2  (128 * AS_LD + 32 * BS2_LD)

// Static scratch
__device__ __nv_bfloat16 g_Wst[16 * 16 * BBLK];          // W_hh bf16, tiled
__device__ float g_WoT [HID * VOC];                      // W_out^T tf32 [k][v]
__device__ float g_GI  [VOC * G3];                       // gi table (incl b_ih)
__device__ float g_H   [2][BSZ * HID];                   // fp32 hidden ping-pong
__device__ float g_Hall[(size_t)(TLEN + 1) * BSZ * HID]; // tf32 hidden (logits in)
__device__ __nv_bfloat16 g_Hab[(size_t)(TLEN + 1) * 256 * ABLK]; // bf16 tiled hidden

__device__ __forceinline__ float tf32r(float x) {
    unsigned u;
    asm("cvt.rna.tf32.f32 %0, %1;" : "=r"(u) : "f"(x));
    return __uint_as_float(u);
}
__device__ __forceinline__ uint32_t smem_u32(const void* p) {
    uint32_t a;
    asm("{ .reg .u64 t; cvta.to.shared.u64 t, %1; cvt.u32.u64 %0, t; }" : "=r"(a) : "l"(p));
    return a;
}
__device__ __forceinline__ void cpa16(const void* dst, const void* src) {
    unsigned d = (unsigned)__cvta_generic_to_shared(dst);
    asm volatile("cp.async.cg.shared.global [%0], [%1], 16;" :: "r"(d), "l"(src));
}
#define CP_COMMIT() asm volatile("cp.async.commit_group;")
#define CP_WAIT(n)  asm volatile("cp.async.wait_group %0;" :: "n"(n))

__device__ __forceinline__ void mb_init(uint32_t a, uint32_t cnt) {
    asm volatile("mbarrier.init.shared.b64 [%0], %1;" :: "r"(a), "r"(cnt) : "memory");
}
__device__ __forceinline__ void mb_wait(uint32_t a, uint32_t parity) {
    asm volatile(
        "{\n\t.reg .pred P;\n\t"
        "W_%=:\n\t"
        "mbarrier.try_wait.parity.acquire.cta.shared::cta.b64 P, [%0], %1, 0x989680;\n\t"
        "@P bra.uni D_%=;\n\t"
        "bra.uni W_%=;\n\t"
        "D_%=:\n\t}"
        :: "r"(a), "r"(parity) : "memory");
}
__device__ __forceinline__ void mb_expect(uint32_t a, uint32_t bytes) {
    asm volatile("mbarrier.arrive.expect_tx.shared.b64 _, [%0], %1;"
                 :: "r"(a), "r"(bytes) : "memory");
}
__device__ __forceinline__ void bulk_g2s(uint32_t dst, const void* src,
                                         uint32_t bytes, uint32_t mbar) {
    asm volatile("cp.async.bulk.shared::cta.global.mbarrier::complete_tx::bytes "
                 "[%0], [%1], %2, [%3];"
                 :: "r"(dst), "l"(src), "r"(bytes), "r"(mbar) : "memory");
}

__device__ __forceinline__ void ldsm4(unsigned& r0, unsigned& r1,
                                      unsigned& r2, unsigned& r3, uint32_t addr) {
    asm volatile("ldmatrix.sync.aligned.m8n8.x4.shared.b16 {%0,%1,%2,%3}, [%4];"
                 : "=r"(r0), "=r"(r1), "=r"(r2), "=r"(r3) : "r"(addr));
}

__device__ __forceinline__ void mmabf(float d[4], const unsigned a[4],
                                      unsigned b0, unsigned b1) {
    asm volatile("mma.sync.aligned.m16n8k16.row.col.f32.bf16.bf16.f32 "
                 "{%0,%1,%2,%3}, {%4,%5,%6,%7}, {%8,%9}, {%0,%1,%2,%3};"
                 : "+f"(d[0]), "+f"(d[1]), "+f"(d[2]), "+f"(d[3])
                 : "r"(a[0]), "r"(a[1]), "r"(a[2]), "r"(a[3]), "r"(b0), "r"(b1));
}
__device__ __forceinline__ void mma8(float d[4], const unsigned a[4],
                                     unsigned b0, unsigned b1) {
    asm volatile("mma.sync.aligned.m16n8k8.row.col.f32.tf32.tf32.f32 "
                 "{%0,%1,%2,%3}, {%4,%5,%6,%7}, {%8,%9}, {%0,%1,%2,%3};"
                 : "+f"(d[0]), "+f"(d[1]), "+f"(d[2]), "+f"(d[3])
                 : "r"(a[0]), "r"(a[1]), "r"(a[2]), "r"(a[3]), "r"(b0), "r"(b1));
}

__device__ __forceinline__ float sigf(float x) {
    return __fdividef(1.f, 1.f + __expf(-x));
}
__device__ __forceinline__ float tanhfast(float x) {
    return 1.f - __fdividef(2.f, __expf(2.f * x) + 1.f);
}

// ---------------------------------------------------------------------------
// Precompute
// ---------------------------------------------------------------------------
__global__ void prep_w(const float* __restrict__ Whh, const float* __restrict__ Wout) {
    const int nB = 16 * 16 * 96 * 32;               // tiled W elements
    const int ntot = nB + HID * VOC;
    for (int idx = blockIdx.x * blockDim.x + threadIdx.x; idx < ntot;
         idx += gridDim.x * blockDim.x) {
        if (idx < nB) {
            int kk  = idx & 31;
            int c   = (idx >> 5) % 96;
            int rest= (idx >> 5) / 96;               // 0..255
            int ktl = rest & 15, jt = rest >> 4;
            int blk = c / 48, r48 = c % 48;
            int g = r48 >> 4, jjw = r48 & 15;
            int n = g * HID + jt * 32 + blk * 16 + jjw;
            int k = ktl * 32 + kk;
            g_Wst[((size_t)(jt * 16 + ktl) * 96 + c) * 40 + kk] =
                __float2bfloat16_rn(Whh[(size_t)n * HID + k]);
        } else {
            int j = idx - nB, v = j / HID, k = j % HID;
            g_WoT[k * VOC + v] = tf32r(Wout[j]);
        }
    }
}

__global__ void prep_gi(const float* __restrict__ emb, const float* __restrict__ Wih,
                        const float* __restrict__ bih) {
    __shared__ float x[EMBD];
    const int v = blockIdx.x;
    if (threadIdx.x < EMBD) x[threadIdx.x] = fmaxf(emb[v * EMBD + threadIdx.x], 0.f);
    __syncthreads();
    for (int n = threadIdx.x; n < G3; n += blockDim.x) {
        float acc = bih[n];
        const float* w = Wih + n * EMBD;
#pragma unroll
        for (int e = 0; e < EMBD; e++) acc += x[e] * w[e];
        g_GI[v * G3 + n] = acc;
    }
}

__global__ void init_h(const float* __restrict__ eh) {
    for (int i = blockIdx.x * blockDim.x + threadIdx.x; i < BSZ * HID;
         i += gridDim.x * blockDim.x) {
        float h = eh[i];
        int b = i >> 9, k = i & 511;
        g_H[0][i]  = h;
        g_Hall[i]  = tf32r(h);
        g_Hab[((size_t)(b >> 7) * 16 + (k >> 5)) * ABLK
              + (size_t)(b & 127) * 40 + (k & 31)] = __float2bfloat16_rn(h);
    }
}

// ---------------------------------------------------------------------------
// GRU step. Grid (16 j, 16 m) = 256 CTAs, 256 threads, 2 CTAs/SM.
// Per K-tile: 2 cp.async.bulk into a 4-stage mbarrier ring; fragments via
// ldmatrix.x4 (4 A + 6 B per tile per warp). Warps 4(M) x 2(N), tile 32x48.
// ---------------------------------------------------------------------------
__global__ void __launch_bounds__(256, 2)
gru_step(int t, const int* __restrict__ tgt, const float* __restrict__ bhh) {
    extern __shared__ __align__(128) unsigned char smraw[];
    __shared__ __align__(8) unsigned long long s_mb[NSTAGE];

    const int tid  = threadIdx.x;
    const int lane = tid & 31, w = tid >> 5;
    const int l3 = lane & 3, q2 = lane >> 2;
    const int wm = (w >> 1) * 32;      // warp M offset (0,32,64,96)
    const int wn = (w & 1);            // warp N group (16 jj)
    const int m0 = blockIdx.y * 128;
    const int j0 = blockIdx.x * 32;
    const int cur = t & 1, nxt = cur ^ 1;

    const uint32_t sb = smem_u32(smraw);
    uint32_t mb[NSTAGE];
#pragma unroll
    for (int s = 0; s < NSTAGE; s++) mb[s] = smem_u32(&s_mb[s]);

    if (tid == 0) {
#pragma unroll
        for (int s = 0; s < NSTAGE; s++) mb_init(mb[s], 1);
    }
    __syncthreads();

    const __nv_bfloat16* __restrict__ Asrc =
        g_Hab + ((size_t)t * 256 + (size_t)blockIdx.y * 16) * ABLK;
    const __nv_bfloat16* __restrict__ Bsrc =
        g_Wst + (size_t)blockIdx.x * 16 * BBLK;

    auto issue = [&](int kt) {
        const int s = kt % NSTAGE;
        const uint32_t as = sb + s * STAGE_BYTES;
        mb_expect(mb[s], STAGE_BYTES);
        bulk_g2s(as,         Asrc + (size_t)kt * ABLK, 10240u, mb[s]);
        bulk_g2s(as + 10240, Bsrc + (size_t)kt * BBLK,  7680u, mb[s]);
    };

    if (tid == 0) { issue(0); issue(1); issue(2); }

    // ---- precomputed ldmatrix lane addresses (byte offsets within a stage) ----
    // A (mf, ks): rows wm+mf*16 + (lane&15), k halves: (lane>>4)*8
    const uint32_t offA = (uint32_t)(wm + (lane & 15)) * 80u + (uint32_t)(lane >> 4) * 16u;
    // B (nf): cols wn*48 + nf*8 + (lane&7); k quarter: (lane>>3)*8
    const uint32_t offB = 10240u + (uint32_t)(wn * 48 + (lane & 7)) * 80u
                        + (uint32_t)(lane >> 3) * 16u;

    float d[2][6][4];
#pragma unroll
    for (int a = 0; a < 2; a++)
#pragma unroll
        for (int b = 0; b < 6; b++)
#pragma unroll
            for (int c = 0; c < 4; c++) d[a][b][c] = 0.f;

    for (int kt = 0; kt < 16; kt++) {
        if (tid == 0 && kt < 13) issue(kt + 3);     // stage (kt+3)%4 freed by
                                                    // syncthreads at end of kt-1
        mb_wait(mb[kt % NSTAGE], (kt >> 2) & 1);

        const uint32_t stg = sb + (kt % NSTAGE) * STAGE_BYTES;

        unsigned a[2][2][4];                        // [ks][mf][4]
#pragma unroll
        for (int mf = 0; mf < 2; mf++)
#pragma unroll
            for (int ks = 0; ks < 2; ks++)
                ldsm4(a[ks][mf][0], a[ks][mf][1], a[ks][mf][2], a[ks][mf][3],
                      stg + offA + (uint32_t)mf * (16u * 80u) + (uint32_t)ks * 32u);

        unsigned b[6][4];                           // [nf][b0ks0,b1ks0,b0ks1,b1ks1]
#pragma unroll
        for (int nf = 0; nf < 6; nf++)
            ldsm4(b[nf][0], b[nf][1], b[nf][2], b[nf][3],
                  stg + offB + (uint32_t)nf * (8u * 80u));

#pragma unroll
        for (int ks = 0; ks < 2; ks++)
#pragma unroll
            for (int nf = 0; nf < 6; nf++) {
                mmabf(d[0][nf], a[ks][0], b[nf][ks * 2], b[nf][ks * 2 + 1]);
                mmabf(d[1][nf], a[ks][1], b[nf][ks * 2], b[nf][ks * 2 + 1]);
            }

        if (kt < 15) __syncthreads();               // release stage kt%4 for reuse
    }

    // ---- register GRU epilogue (fp32 math, fast exp) ----
    const float* __restrict__ Hc = g_H[cur];
    float* __restrict__ Hn  = g_H[nxt];
    float* __restrict__ Ha  = g_Hall + (size_t)(t + 1) * BSZ * HID;
    __nv_bfloat16* __restrict__ Hb =
        g_Hab + ((size_t)(t + 1) * 256 + (size_t)blockIdx.y * 16 + blockIdx.x) * ABLK;
#pragma unroll
    for (int mf = 0; mf < 2; mf++) {
#pragma unroll
        for (int rh = 0; rh < 2; rh++) {
            const int lrow = wm + mf * 16 + q2 + rh * 8;
            const int row  = m0 + lrow;
            const int tok = (t == 0) ? 0 : __ldg(tgt + row * TLEN + t - 1);
            const float* __restrict__ gi = g_GI + tok * G3;
#pragma unroll
            for (int jf = 0; jf < 2; jf++) {
                const int lcol = wn * 16 + jf * 8 + l3 * 2;
                const int j2 = j0 + lcol;
                float h[2];
#pragma unroll
                for (int p = 0; p < 2; p++) {
                    const int r = rh * 2 + p;
                    const int j = j2 + p;
                    float gr  = d[mf][jf][r]     + bhh[j]         + gi[j];
                    float gz  = d[mf][2 + jf][r] + bhh[HID + j]   + gi[HID + j];
                    float ghn = d[mf][4 + jf][r] + bhh[2*HID + j];
                    float rr = sigf(gr);
                    float zz = sigf(gz);
                    float nn = tanhfast(gi[2*HID + j] + rr * ghn);
                    float ho = Hc[(size_t)row * HID + j];
                    h[p] = fmaf(zz, ho - nn, nn);   // (1-z)n + z*ho
                }
                *reinterpret_cast<float2*>(Hn + (size_t)row * HID + j2) =
                    make_float2(h[0], h[1]);
                *reinterpret_cast<float2*>(Ha + (size_t)row * HID + j2) =
                    make_float2(tf32r(h[0]), tf32r(h[1]));
                *reinterpret_cast<__nv_bfloat162*>(Hb + (size_t)lrow * 40 + lcol) =
                    __floats2bfloat162_rn(h[0], h[1]);
            }
        }
    }
}

// ---------------------------------------------------------------------------
// Batched logits (tf32, proven): (160*2048) x 128 x 512 GEMM + log_softmax.
// ---------------------------------------------------------------------------
__global__ void __launch_bounds__(256, 1)
logits_all(const float* __restrict__ bout, float* __restrict__ out) {
    extern __shared__ float sm[];
    float* ep = sm;

    const int tid = threadIdx.x, lane = tid & 31, w = tid >> 5;
    const int l3 = lane & 3, q2 = lane >> 2;
    const int wm = (w >> 1) * 32, wn = (w & 1) * 64;
    const int m0 = blockIdx.x * 128;

    const float* __restrict__ A = g_Hall + (size_t)BSZ * HID;   // slots 1..160

    float d[2][8][4];
#pragma unroll
    for (int a = 0; a < 2; a++)
#pragma unroll
        for (int b = 0; b < 8; b++)
#pragma unroll
            for (int c = 0; c < 4; c++) d[a][b][c] = 0.f;

    auto load_tile = [&](int buf, int k0) {
        float* As = sm + buf * SBUF2;
        float* Bs = As + 128 * AS_LD;
#pragma unroll
        for (int i = 0; i < 4; i++) {
            int f = i * 256 + tid, row = f >> 3, q = f & 7;
            cpa16(As + row * AS_LD + q * 4, A + (size_t)(m0 + row) * HID + k0 + q * 4);
        }
#pragma unroll
        for (int i = 0; i < 4; i++) {
            int f = i * 256 + tid, k = f >> 5, q = f & 31;
            cpa16(Bs + k * BS2_LD + q * 4, g_WoT + (k0 + k) * VOC + q * 4);
        }
    };

    load_tile(0, 0);
    CP_COMMIT();
    CP_WAIT(0);
    __syncthreads();

    for (int kt = 0; kt < 16; kt++) {
        if (kt < 15) { load_tile((kt + 1) & 1, (kt + 1) * 32); CP_COMMIT(); }
        const float* As = sm + (kt & 1) * SBUF2;
        const float* Bs = As + 128 * AS_LD;
#pragma unroll
        for (int ks = 0; ks < 4; ks++) {
            const int kk = ks * 8;
            unsigned a[2][4];
#pragma unroll
            for (int mf = 0; mf < 2; mf++) {
                int r = wm + mf * 16 + q2;
                a[mf][0] = __float_as_uint(As[r * AS_LD + kk + l3]);
                a[mf][1] = __float_as_uint(As[(r + 8) * AS_LD + kk + l3]);
                a[mf][2] = __float_as_uint(As[r * AS_LD + kk + 4 + l3]);
                a[mf][3] = __float_as_uint(As[(r + 8) * AS_LD + kk + 4 + l3]);
            }
#pragma unroll
            for (int nf = 0; nf < 8; nf++) {
                int col = wn + nf * 8 + q2;
                unsigned b0 = __float_as_uint(Bs[(kk + l3) * BS2_LD + col]);
                unsigned b1 = __float_as_uint(Bs[(kk + 4 + l3) * BS2_LD + col]);
                mma8(d[0][nf], a[0], b0, b1);
                mma8(d[1][nf], a[1], b0, b1);
            }
        }
        if (kt < 15) { CP_WAIT(0); __syncthreads(); }
    }

    __syncthreads();

#pragma unroll
    for (int mf = 0; mf < 2; mf++)
#pragma unroll
        for (int nf = 0; nf < 8; nf++)
#pragma unroll
            for (int rh = 0; rh < 2; rh++) {
                int r = wm + mf * 16 + q2 + rh * 8;
                int col = wn + nf * 8 + l3 * 2;
                *reinterpret_cast<float2*>(ep + r * EP_LD + col) =
                    make_float2(d[mf][nf][rh * 2], d[mf][nf][rh * 2 + 1]);
            }
    __syncthreads();

    for (int i = 0; i < 16; i++) {
        int row = w * 16 + i;
        float x[4];
        float mx = -1e30f;
#pragma unroll
        for (int q = 0; q < 4; q++) {
            int v = lane + q * 32;
            x[q] = ep[row * EP_LD + v] + bout[v];
            mx = fmaxf(mx, x[q]);
        }
#pragma unroll
        for (int off = 16; off > 0; off >>= 1)
            mx = fmaxf(mx, __shfl_xor_sync(0xffffffffu, mx, off));
        float s = 0.f;
#pragma unroll
        for (int q = 0; q < 4; q++) s += expf(x[q] - mx);
#pragma unroll
        for (int off = 16; off > 0; off >>= 1)
            s += __shfl_xor_sync(0xffffffffu, s, off);
        float L = mx + logf(s);
        float* orow = out + (size_t)(m0 + row) * VOC;
#pragma unroll
        for (int q = 0; q < 4; q++) orow[lane + q * 32] = x[q] - L;
    }
}

__global__ void finalize_h(float* __restrict__ out) {
    float* dst = out + (size_t)TLEN * BSZ * VOC;
    for (int i = blockIdx.x * blockDim.x + threadIdx.x; i < BSZ * HID;
         i += gridDim.x * blockDim.x)
        dst[i] = g_H[0][i];   // after t=159: nxt = 0
}

// ---------------------------------------------------------------------------
extern "C" void kernel_launch(void* const* d_in, const int* in_sizes, int n_in,
                              void* d_out, int out_size) {
    (void)in_sizes; (void)n_in; (void)out_size;
    const float* enc_h = (const float*)d_in[1];
    const int*   tgt   = (const int*)d_in[2];
    const float* emb   = (const float*)d_in[3];
    const float* Wih   = (const float*)d_in[4];
    const float* Whh   = (const float*)d_in[5];
    const float* bih   = (const float*)d_in[6];
    const float* bhh   = (const float*)d_in[7];
    const float* Wout  = (const float*)d_in[8];
    const float* bout  = (const float*)d_in[9];
    float* out = (float*)d_out;

    const int gru_smem = NSTAGE * STAGE_BYTES;   // 71680 B (x2 CTAs/SM)
    const int log_smem = 2 * SBUF2 * 4;          // 71680 B
    cudaFuncSetAttribute(gru_step,   cudaFuncAttributeMaxDynamicSharedMemorySize, gru_smem);
    cudaFuncSetAttribute(logits_all, cudaFuncAttributeMaxDynamicSharedMemorySize, log_smem);

    prep_w <<<512, 256>>>(Whh, Wout);
    prep_gi<<<VOC, 256>>>(emb, Wih, bih);
    init_h <<<1024, 256>>>(enc_h);

    for (int t = 0; t < TLEN; t++)
        gru_step<<<dim3(16, 16), 256, gru_smem>>>(t, tgt, bhh);

    logits_all<<<(TLEN * BSZ) / 128, 256, log_smem>>>(bout, out);
    finalize_h<<<1024, 256>>>(out);
}

// round 15
// speedup vs baseline: 2.1348x; 1.0254x over previous
#include <cuda_runtime.h>
#include <cuda_bf16.h>
#include <cstdint>
#include <cmath>

// ---------------------------------------------------------------------------
// DecoderRNN, persistent-GRU edition:
//  * ONE persistent kernel runs all 160 GRU steps. Step dependency is
//    per-m-block (A-tile k-cols of step t+1 come only from column-m CTAs at
//    step t) -> 16-CTA release/acquire barriers per m-block, not global.
//  * Split bulk-copy rings: B (weights) prefetch crosses the barrier; A waits.
//  * Fragments via ldmatrix.x4; mma m16n8k16 bf16; fp32 gates; identical
//    numerics to R14 (rel_err 5.52e-4).
//  * tf32 hidden history -> ONE batched logits GEMM + fused log_softmax.
// Output: [160*2048*128 log_probs fp32][2048*512 final hidden fp32]
// ---------------------------------------------------------------------------

#define HID   512
#define VOC   128
#define EMBD  64
#define BSZ   2048
#define TLEN  160
#define G3    1536

#define ABLK   (128 * 40)            // 10240 B per A tile
#define BBLK   (96 * 40)             //  7680 B per B tile
#define A_RING (4 * 10240)           // 40960
#define B_RING (4 * 7680)            // 30720
#define GRU_SMEM (A_RING + B_RING)   // 71680

// logits tf32 tiling (proven path, unchanged)
#define AS_LD  36
#define BS2_LD 136
#define EP_LD  132
#define SBUF2  (128 * AS_LD + 32 * BS2_LD)

// Static scratch
__device__ __nv_bfloat16 g_Wst[16 * 16 * BBLK];          // W_hh bf16, tiled
__device__ float g_WoT [HID * VOC];                      // W_out^T tf32 [k][v]
__device__ float g_GI  [VOC * G3];                       // gi table (incl b_ih)
__device__ float g_H   [2][BSZ * HID];                   // fp32 hidden ping-pong
__device__ float g_Hall[(size_t)(TLEN + 1) * BSZ * HID]; // tf32 hidden (logits in)
__device__ __nv_bfloat16 g_Hab[(size_t)(TLEN + 1) * 256 * ABLK]; // bf16 tiled hidden
__device__ unsigned g_mbar[16 * 32];                     // per-m barriers, 128B apart

__device__ __forceinline__ float tf32r(float x) {
    unsigned u;
    asm("cvt.rna.tf32.f32 %0, %1;" : "=r"(u) : "f"(x));
    return __uint_as_float(u);
}
__device__ __forceinline__ uint32_t smem_u32(const void* p) {
    uint32_t a;
    asm("{ .reg .u64 t; cvta.to.shared.u64 t, %1; cvt.u32.u64 %0, t; }" : "=r"(a) : "l"(p));
    return a;
}
__device__ __forceinline__ void cpa16(const void* dst, const void* src) {
    unsigned d = (unsigned)__cvta_generic_to_shared(dst);
    asm volatile("cp.async.cg.shared.global [%0], [%1], 16;" :: "r"(d), "l"(src));
}
#define CP_COMMIT() asm volatile("cp.async.commit_group;")
#define CP_WAIT(n)  asm volatile("cp.async.wait_group %0;" :: "n"(n))

__device__ __forceinline__ void mb_init(uint32_t a, uint32_t cnt) {
    asm volatile("mbarrier.init.shared.b64 [%0], %1;" :: "r"(a), "r"(cnt) : "memory");
}
__device__ __forceinline__ void mb_wait(uint32_t a, uint32_t parity) {
    asm volatile(
        "{\n\t.reg .pred P;\n\t"
        "W_%=:\n\t"
        "mbarrier.try_wait.parity.acquire.cta.shared::cta.b64 P, [%0], %1, 0x989680;\n\t"
        "@P bra.uni D_%=;\n\t"
        "bra.uni W_%=;\n\t"
        "D_%=:\n\t}"
        :: "r"(a), "r"(parity) : "memory");
}
__device__ __forceinline__ void mb_expect(uint32_t a, uint32_t bytes) {
    asm volatile("mbarrier.arrive.expect_tx.shared.b64 _, [%0], %1;"
                 :: "r"(a), "r"(bytes) : "memory");
}
__device__ __forceinline__ void bulk_g2s(uint32_t dst, const void* src,
                                         uint32_t bytes, uint32_t mbar) {
    asm volatile("cp.async.bulk.shared::cta.global.mbarrier::complete_tx::bytes "
                 "[%0], [%1], %2, [%3];"
                 :: "r"(dst), "l"(src), "r"(bytes), "r"(mbar) : "memory");
}

__device__ __forceinline__ void ldsm4(unsigned& r0, unsigned& r1,
                                      unsigned& r2, unsigned& r3, uint32_t addr) {
    asm volatile("ldmatrix.sync.aligned.m8n8.x4.shared.b16 {%0,%1,%2,%3}, [%4];"
                 : "=r"(r0), "=r"(r1), "=r"(r2), "=r"(r3) : "r"(addr));
}
__device__ __forceinline__ void mmabf(float d[4], const unsigned a[4],
                                      unsigned b0, unsigned b1) {
    asm volatile("mma.sync.aligned.m16n8k16.row.col.f32.bf16.bf16.f32 "
                 "{%0,%1,%2,%3}, {%4,%5,%6,%7}, {%8,%9}, {%0,%1,%2,%3};"
                 : "+f"(d[0]), "+f"(d[1]), "+f"(d[2]), "+f"(d[3])
                 : "r"(a[0]), "r"(a[1]), "r"(a[2]), "r"(a[3]), "r"(b0), "r"(b1));
}
__device__ __forceinline__ void mma8(float d[4], const unsigned a[4],
                                     unsigned b0, unsigned b1) {
    asm volatile("mma.sync.aligned.m16n8k8.row.col.f32.tf32.tf32.f32 "
                 "{%0,%1,%2,%3}, {%4,%5,%6,%7}, {%8,%9}, {%0,%1,%2,%3};"
                 : "+f"(d[0]), "+f"(d[1]), "+f"(d[2]), "+f"(d[3])
                 : "r"(a[0]), "r"(a[1]), "r"(a[2]), "r"(a[3]), "r"(b0), "r"(b1));
}

__device__ __forceinline__ float sigf(float x) {
    return __fdividef(1.f, 1.f + __expf(-x));
}
__device__ __forceinline__ float tanhfast(float x) {
    return 1.f - __fdividef(2.f, __expf(2.f * x) + 1.f);
}

// ---------------------------------------------------------------------------
// Precompute
// ---------------------------------------------------------------------------
__global__ void prep_w(const float* __restrict__ Whh, const float* __restrict__ Wout) {
    const int nB = 16 * 16 * 96 * 32;
    const int ntot = nB + HID * VOC;
    for (int idx = blockIdx.x * blockDim.x + threadIdx.x; idx < ntot;
         idx += gridDim.x * blockDim.x) {
        if (idx < nB) {
            int kk  = idx & 31;
            int c   = (idx >> 5) % 96;
            int rest= (idx >> 5) / 96;
            int ktl = rest & 15, jt = rest >> 4;
            int blk = c / 48, r48 = c % 48;
            int g = r48 >> 4, jjw = r48 & 15;
            int n = g * HID + jt * 32 + blk * 16 + jjw;
            int k = ktl * 32 + kk;
            g_Wst[((size_t)(jt * 16 + ktl) * 96 + c) * 40 + kk] =
                __float2bfloat16_rn(Whh[(size_t)n * HID + k]);
        } else {
            int j = idx - nB, v = j / HID, k = j % HID;
            g_WoT[k * VOC + v] = tf32r(Wout[j]);
        }
    }
}

__global__ void prep_gi(const float* __restrict__ emb, const float* __restrict__ Wih,
                        const float* __restrict__ bih) {
    __shared__ float x[EMBD];
    const int v = blockIdx.x;
    if (threadIdx.x < EMBD) x[threadIdx.x] = fmaxf(emb[v * EMBD + threadIdx.x], 0.f);
    __syncthreads();
    for (int n = threadIdx.x; n < G3; n += blockDim.x) {
        float acc = bih[n];
        const float* w = Wih + n * EMBD;
#pragma unroll
        for (int e = 0; e < EMBD; e++) acc += x[e] * w[e];
        g_GI[v * G3 + n] = acc;
    }
}

__global__ void init_h(const float* __restrict__ eh) {
    if (blockIdx.x == 0)
        for (int q = threadIdx.x; q < 16 * 32; q += blockDim.x) g_mbar[q] = 0;
    for (int i = blockIdx.x * blockDim.x + threadIdx.x; i < BSZ * HID;
         i += gridDim.x * blockDim.x) {
        float h = eh[i];
        int b = i >> 9, k = i & 511;
        g_H[0][i]  = h;
        g_Hall[i]  = tf32r(h);
        g_Hab[((size_t)(b >> 7) * 16 + (k >> 5)) * ABLK
              + (size_t)(b & 127) * 40 + (k & 31)] = __float2bfloat16_rn(h);
    }
}

// ---------------------------------------------------------------------------
// Persistent GRU: all 160 steps in one launch. Grid (16 j, 16 m) = 256 CTAs,
// 256 threads, 2 CTAs/SM (all co-resident). Per-m 16-CTA barriers per step.
// Split 4-deep A/B bulk rings; B prefetch crosses the barrier.
// ---------------------------------------------------------------------------
__global__ void __launch_bounds__(256, 2)
gru_persist(const int* __restrict__ tgt, const float* __restrict__ bhh) {
    extern __shared__ __align__(128) unsigned char smraw[];
    __shared__ __align__(8) unsigned long long s_mbA[4], s_mbB[4];

    const int tid  = threadIdx.x;
    const int lane = tid & 31, w = tid >> 5;
    const int l3 = lane & 3, q2 = lane >> 2;
    const int wm = (w >> 1) * 32;
    const int wn = (w & 1);
    const int m0 = blockIdx.y * 128;
    const int j0 = blockIdx.x * 32;

    const uint32_t sbA = smem_u32(smraw);
    const uint32_t sbB = sbA + A_RING;
    uint32_t mbA[4], mbB[4];
#pragma unroll
    for (int s = 0; s < 4; s++) { mbA[s] = smem_u32(&s_mbA[s]); mbB[s] = smem_u32(&s_mbB[s]); }

    if (tid == 0) {
#pragma unroll
        for (int s = 0; s < 4; s++) { mb_init(mbA[s], 1); mb_init(mbB[s], 1); }
    }
    __syncthreads();

    const __nv_bfloat16* __restrict__ Bsrc = g_Wst + (size_t)blockIdx.x * 16 * BBLK;
    unsigned* const barp = &g_mbar[blockIdx.y * 32];

    auto issueA = [&](int c) {       // c = global tile counter (16t + kt)
        const int s = c & 3;
        mb_expect(mbA[s], 10240u);
        const __nv_bfloat16* src = g_Hab +
            ((size_t)(c >> 4) * 256 + (size_t)blockIdx.y * 16 + (c & 15)) * ABLK;
        bulk_g2s(sbA + (uint32_t)s * 10240u, src, 10240u, mbA[s]);
    };
    auto issueB = [&](int c) {
        const int s = c & 3;
        mb_expect(mbB[s], 7680u);
        bulk_g2s(sbB + (uint32_t)s * 7680u, Bsrc + (size_t)(c & 15) * BBLK, 7680u, mbB[s]);
    };

    if (tid == 0) { issueB(0); issueB(1); issueB(2); issueA(0); issueA(1); issueA(2); }

    // ldmatrix lane offsets (within one ring slot)
    const uint32_t offA = (uint32_t)(wm + (lane & 15)) * 80u + (uint32_t)(lane >> 4) * 16u;
    const uint32_t offB = (uint32_t)(wn * 48 + (lane & 7)) * 80u + (uint32_t)(lane >> 3) * 16u;

    for (int t = 0; t < TLEN; t++) {
        const int base = t << 4;

        float d[2][6][4];
#pragma unroll
        for (int a = 0; a < 2; a++)
#pragma unroll
            for (int b = 0; b < 6; b++)
#pragma unroll
                for (int c = 0; c < 4; c++) d[a][b][c] = 0.f;

        for (int kt = 0; kt < 16; kt++) {
            const int c = base + kt;
            if (tid == 0) {
                if (c + 3 < TLEN * 16) issueB(c + 3);
                if (kt < 13) issueA(c + 3);       // same-step A only
            }
            const uint32_t par = (uint32_t)((c >> 2) & 1);
            mb_wait(mbA[c & 3], par);
            mb_wait(mbB[c & 3], par);

            const uint32_t stA = sbA + (uint32_t)(c & 3) * 10240u;
            const uint32_t stB = sbB + (uint32_t)(c & 3) * 7680u;

            unsigned a[2][2][4];                  // [ks][mf][4]
#pragma unroll
            for (int mf = 0; mf < 2; mf++)
#pragma unroll
                for (int ks = 0; ks < 2; ks++)
                    ldsm4(a[ks][mf][0], a[ks][mf][1], a[ks][mf][2], a[ks][mf][3],
                          stA + offA + (uint32_t)mf * (16u * 80u) + (uint32_t)ks * 32u);

            unsigned b[6][4];
#pragma unroll
            for (int nf = 0; nf < 6; nf++)
                ldsm4(b[nf][0], b[nf][1], b[nf][2], b[nf][3],
                      stB + offB + (uint32_t)nf * (8u * 80u));

#pragma unroll
            for (int ks = 0; ks < 2; ks++)
#pragma unroll
                for (int nf = 0; nf < 6; nf++) {
                    mmabf(d[0][nf], a[ks][0], b[nf][ks * 2], b[nf][ks * 2 + 1]);
                    mmabf(d[1][nf], a[ks][1], b[nf][ks * 2], b[nf][ks * 2 + 1]);
                }

            if (kt < 15) __syncthreads();         // release ring slot
        }

        // ---- register GRU epilogue (identical math to R14) ----
        const int cur = t & 1, nxt = cur ^ 1;
        const float* __restrict__ Hc = g_H[cur];
        float* __restrict__ Hn  = g_H[nxt];
        float* __restrict__ Ha  = g_Hall + (size_t)(t + 1) * BSZ * HID;
        __nv_bfloat16* __restrict__ Hb =
            g_Hab + ((size_t)(t + 1) * 256 + (size_t)blockIdx.y * 16 + blockIdx.x) * ABLK;
#pragma unroll
        for (int mf = 0; mf < 2; mf++) {
#pragma unroll
            for (int rh = 0; rh < 2; rh++) {
                const int lrow = wm + mf * 16 + q2 + rh * 8;
                const int row  = m0 + lrow;
                const int tok = (t == 0) ? 0 : __ldg(tgt + row * TLEN + t - 1);
                const float* __restrict__ gi = g_GI + tok * G3;
#pragma unroll
                for (int jf = 0; jf < 2; jf++) {
                    const int lcol = wn * 16 + jf * 8 + l3 * 2;
                    const int j2 = j0 + lcol;
                    float h[2];
#pragma unroll
                    for (int p = 0; p < 2; p++) {
                        const int r = rh * 2 + p;
                        const int j = j2 + p;
                        float gr  = d[mf][jf][r]     + bhh[j]         + gi[j];
                        float gz  = d[mf][2 + jf][r] + bhh[HID + j]   + gi[HID + j];
                        float ghn = d[mf][4 + jf][r] + bhh[2*HID + j];
                        float rr = sigf(gr);
                        float zz = sigf(gz);
                        float nn = tanhfast(gi[2*HID + j] + rr * ghn);
                        float ho = Hc[(size_t)row * HID + j];
                        h[p] = fmaf(zz, ho - nn, nn);
                    }
                    *reinterpret_cast<float2*>(Hn + (size_t)row * HID + j2) =
                        make_float2(h[0], h[1]);
                    *reinterpret_cast<float2*>(Ha + (size_t)row * HID + j2) =
                        make_float2(tf32r(h[0]), tf32r(h[1]));
                    *reinterpret_cast<__nv_bfloat162*>(Hb + (size_t)lrow * 40 + lcol) =
                        __floats2bfloat162_rn(h[0], h[1]);
                }
            }
        }

        // ---- per-m-block barrier (16 CTAs) + next-step A issues ----
        if (t < TLEN - 1) {
            __syncthreads();                      // all epilogue stores done
            if (tid == 0) {
                asm volatile("red.release.gpu.add.u32 [%0], %1;"
                             :: "l"(barp), "r"(1u) : "memory");
                const unsigned target = 16u * (unsigned)(t + 1);
                unsigned v;
                do {
                    asm volatile("ld.acquire.gpu.u32 %0, [%1];"
                                 : "=r"(v) : "l"(barp) : "memory");
                    if (v < target) __nanosleep(64);
                } while (v < target);
                asm volatile("fence.proxy.async;" ::: "memory");
                issueA(base + 16); issueA(base + 17); issueA(base + 18);
            }
            __syncthreads();
        }
    }
}

// ---------------------------------------------------------------------------
// Batched logits (tf32, proven): (160*2048) x 128 x 512 GEMM + log_softmax.
// ---------------------------------------------------------------------------
__global__ void __launch_bounds__(256, 1)
logits_all(const float* __restrict__ bout, float* __restrict__ out) {
    extern __shared__ float sm[];
    float* ep = sm;

    const int tid = threadIdx.x, lane = tid & 31, w = tid >> 5;
    const int l3 = lane & 3, q2 = lane >> 2;
    const int wm = (w >> 1) * 32, wn = (w & 1) * 64;
    const int m0 = blockIdx.x * 128;

    const float* __restrict__ A = g_Hall + (size_t)BSZ * HID;

    float d[2][8][4];
#pragma unroll
    for (int a = 0; a < 2; a++)
#pragma unroll
        for (int b = 0; b < 8; b++)
#pragma unroll
            for (int c = 0; c < 4; c++) d[a][b][c] = 0.f;

    auto load_tile = [&](int buf, int k0) {
        float* As = sm + buf * SBUF2;
        float* Bs = As + 128 * AS_LD;
#pragma unroll
        for (int i = 0; i < 4; i++) {
            int f = i * 256 + tid, row = f >> 3, q = f & 7;
            cpa16(As + row * AS_LD + q * 4, A + (size_t)(m0 + row) * HID + k0 + q * 4);
        }
#pragma unroll
        for (int i = 0; i < 4; i++) {
            int f = i * 256 + tid, k = f >> 5, q = f & 31;
            cpa16(Bs + k * BS2_LD + q * 4, g_WoT + (k0 + k) * VOC + q * 4);
        }
    };

    load_tile(0, 0);
    CP_COMMIT();
    CP_WAIT(0);
    __syncthreads();

    for (int kt = 0; kt < 16; kt++) {
        if (kt < 15) { load_tile((kt + 1) & 1, (kt + 1) * 32); CP_COMMIT(); }
        const float* As = sm + (kt & 1) * SBUF2;
        const float* Bs = As + 128 * AS_LD;
#pragma unroll
        for (int ks = 0; ks < 4; ks++) {
            const int kk = ks * 8;
            unsigned a[2][4];
#pragma unroll
            for (int mf = 0; mf < 2; mf++) {
                int r = wm + mf * 16 + q2;
                a[mf][0] = __float_as_uint(As[r * AS_LD + kk + l3]);
                a[mf][1] = __float_as_uint(As[(r + 8) * AS_LD + kk + l3]);
                a[mf][2] = __float_as_uint(As[r * AS_LD + kk + 4 + l3]);
                a[mf][3] = __float_as_uint(As[(r + 8) * AS_LD + kk + 4 + l3]);
            }
#pragma unroll
            for (int nf = 0; nf < 8; nf++) {
                int col = wn + nf * 8 + q2;
                unsigned b0 = __float_as_uint(Bs[(kk + l3) * BS2_LD + col]);
                unsigned b1 = __float_as_uint(Bs[(kk + 4 + l3) * BS2_LD + col]);
                mma8(d[0][nf], a[0], b0, b1);
                mma8(d[1][nf], a[1], b0, b1);
            }
        }
        if (kt < 15) { CP_WAIT(0); __syncthreads(); }
    }

    __syncthreads();

#pragma unroll
    for (int mf = 0; mf < 2; mf++)
#pragma unroll
        for (int nf = 0; nf < 8; nf++)
#pragma unroll
            for (int rh = 0; rh < 2; rh++) {
                int r = wm + mf * 16 + q2 + rh * 8;
                int col = wn + nf * 8 + l3 * 2;
                *reinterpret_cast<float2*>(ep + r * EP_LD + col) =
                    make_float2(d[mf][nf][rh * 2], d[mf][nf][rh * 2 + 1]);
            }
    __syncthreads();

    for (int i = 0; i < 16; i++) {
        int row = w * 16 + i;
        float x[4];
        float mx = -1e30f;
#pragma unroll
        for (int q = 0; q < 4; q++) {
            int v = lane + q * 32;
            x[q] = ep[row * EP_LD + v] + bout[v];
            mx = fmaxf(mx, x[q]);
        }
#pragma unroll
        for (int off = 16; off > 0; off >>= 1)
            mx = fmaxf(mx, __shfl_xor_sync(0xffffffffu, mx, off));
        float s = 0.f;
#pragma unroll
        for (int q = 0; q < 4; q++) s += expf(x[q] - mx);
#pragma unroll
        for (int off = 16; off > 0; off >>= 1)
            s += __shfl_xor_sync(0xffffffffu, s, off);
        float L = mx + logf(s);
        float* orow = out + (size_t)(m0 + row) * VOC;
#pragma unroll
        for (int q = 0; q < 4; q++) orow[lane + q * 32] = x[q] - L;
    }
}

__global__ void finalize_h(float* __restrict__ out) {
    float* dst = out + (size_t)TLEN * BSZ * VOC;
    for (int i = blockIdx.x * blockDim.x + threadIdx.x; i < BSZ * HID;
         i += gridDim.x * blockDim.x)
        dst[i] = g_H[0][i];   // after t=159: nxt = 0
}

// ---------------------------------------------------------------------------
extern "C" void kernel_launch(void* const* d_in, const int* in_sizes, int n_in,
                              void* d_out, int out_size) {
    (void)in_sizes; (void)n_in; (void)out_size;
    const float* enc_h = (const float*)d_in[1];
    const int*   tgt   = (const int*)d_in[2];
    const float* emb   = (const float*)d_in[3];
    const float* Wih   = (const float*)d_in[4];
    const float* Whh   = (const float*)d_in[5];
    const float* bih   = (const float*)d_in[6];
    const float* bhh   = (const float*)d_in[7];
    const float* Wout  = (const float*)d_in[8];
    const float* bout  = (const float*)d_in[9];
    float* out = (float*)d_out;

    const int log_smem = 2 * SBUF2 * 4;          // 71680 B
    cudaFuncSetAttribute(gru_persist, cudaFuncAttributeMaxDynamicSharedMemorySize, GRU_SMEM);
    cudaFuncSetAttribute(logits_all,  cudaFuncAttributeMaxDynamicSharedMemorySize, log_smem);

    prep_w <<<512, 256>>>(Whh, Wout);
    prep_gi<<<VOC, 256>>>(emb, Wih, bih);
    init_h <<<1024, 256>>>(enc_h);

    gru_persist<<<dim3(16, 16), 256, GRU_SMEM>>>(tgt, bhh);

    logits_all<<<(TLEN * BSZ) / 128, 256, log_smem>>>(bout, out);
    finalize_h<<<1024, 256>>>(out);
}